// round 8
// baseline (speedup 1.0000x reference)
#include <cuda_runtime.h>
#include <math.h>
#include <stdint.h>

// Problem dims (fixed)
#define SEQ 256
#define BATCH 32
#define EDIM 256
#define HDIM 512
#define GDIM 2048           // 4*H
#define TTAGS 10
#define START_TAG 8
#define STOP_TAG 9
#define NEGV -10000.0f

#define NBLK 128            // 2 dir x 32 unit-chunks x 2 batch-halves

// packed fp32x2 helpers (sm_103a native; ptxas never emits from C++)
#define FMA2(acc, a, b) asm("fma.rn.f32x2 %0, %1, %2, %3;" : "=l"(acc) : "l"(a), "l"(b), "l"(acc))
#define SPLAT2(d, s)    asm("mov.b64 %0, {%1, %1};" : "=l"(d) : "f"(s))
#define UNPK2(lo, hi, s) asm("mov.b64 {%0, %1}, %2;" : "=f"(lo), "=f"(hi) : "l"(s))

// ---------------- scratch (static device globals; no runtime alloc) ----------
// Pre-activations: [d][gate][m][j], m = t*32+b (8192), j = 0..511
__device__ float g_xg2[2u * 4 * (SEQ * BATCH) * HDIM];
__device__ float g_hseq[2u * SEQ * BATCH * HDIM];      // hidden states [d][t][b][j]
__device__ float g_hzero[BATCH * HDIM];                // never written -> stays zero
__device__ float g_feats[SEQ * BATCH * TTAGS];         // emissions
__device__ int   g_arrive[NBLK];                       // per-block arrival epochs

__device__ __forceinline__ uint32_t smem_u32(const void* p) {
    uint32_t a;
    asm("{ .reg .u64 t; cvta.to.shared.u64 t, %1; cvt.u32.u64 %0, t; }" : "=r"(a) : "l"(p));
    return a;
}

__device__ __forceinline__ void mbar_wait(uint32_t addr, uint32_t par) {
    asm volatile(
        "{\n\t.reg .pred P;\n"
        "LW_%=:\n\t"
        "mbarrier.try_wait.parity.acquire.cta.shared::cta.b64 P, [%0], %1, 0x989680;\n\t"
        "@P bra LD_%=;\n\t"
        "bra LW_%=;\n"
        "LD_%=:\n\t}"
        :: "r"(addr), "r"(par) : "memory");
}

// ---------------------------------------------------------------------------
// Dummy kernels: shift the ncu capture window (-s 5 -c 1) onto recur_kernel.
// ---------------------------------------------------------------------------
__global__ void dummy_kernel() {}

// ---------------------------------------------------------------------------
// Kernel 1: xg2[d][gate][m][j] = sum_e emb[tok[m]][e] * w_ih_d[gate*512+j][e] + b
// BM=128 (m=(t,b)), BN=128, BK=16, 256 thr, 8x8 microtile (fp32x2 along m).
// n-tile (128) never straddles a gate boundary (512), so store is simple.
// ---------------------------------------------------------------------------
__global__ void __launch_bounds__(256) xg_kernel(
    const int* __restrict__ tokens, const float* __restrict__ emb,
    const float* __restrict__ wf, const float* __restrict__ bf,
    const float* __restrict__ wb, const float* __restrict__ bb)
{
    const int bm = blockIdx.x;          // 64
    const int bn = blockIdx.y;          // 16
    const int dir = blockIdx.z;         // 2
    const int tid = threadIdx.x;

    const float* w    = dir ? wb : wf;
    const float* bias = dir ? bb : bf;

    __shared__ int   rowtok[128];
    __shared__ __align__(16) float As[16 * 132];
    __shared__ __align__(16) float Bs[16 * 132];

    if (tid < 128) {
        int mg = bm * 128 + tid;                 // m = t*32 + b
        rowtok[tid] = tokens[(mg & 31) * SEQ + (mg >> 5)];
    }
    __syncthreads();

    const int ty = tid >> 4;   // 0..15 -> 8 rows (m)
    const int tx = tid & 15;   // 0..15 -> 8 cols (n)

    uint64_t acc[4][8];        // [m-pair][n], packed f32x2 along m
    #pragma unroll
    for (int i = 0; i < 4; i++)
        #pragma unroll
        for (int j = 0; j < 8; j++) acc[i][j] = 0ull;

    for (int k0 = 0; k0 < EDIM; k0 += 16) {
        #pragma unroll
        for (int it = 0; it < 2; ++it) {
            int f4 = tid + it * 256;
            int m = f4 >> 2, kq = f4 & 3;
            float4 v = *(const float4*)(emb + (size_t)rowtok[m] * EDIM + k0 + kq * 4);
            As[(kq * 4 + 0) * 132 + m] = v.x;
            As[(kq * 4 + 1) * 132 + m] = v.y;
            As[(kq * 4 + 2) * 132 + m] = v.z;
            As[(kq * 4 + 3) * 132 + m] = v.w;
        }
        #pragma unroll
        for (int it = 0; it < 2; ++it) {
            int f4 = tid + it * 256;
            int n = f4 >> 2, kq = f4 & 3;
            float4 v = *(const float4*)(w + (size_t)(bn * 128 + n) * EDIM + k0 + kq * 4);
            Bs[(kq * 4 + 0) * 132 + n] = v.x;
            Bs[(kq * 4 + 1) * 132 + n] = v.y;
            Bs[(kq * 4 + 2) * 132 + n] = v.z;
            Bs[(kq * 4 + 3) * 132 + n] = v.w;
        }
        __syncthreads();
        #pragma unroll
        for (int k = 0; k < 16; k++) {
            ulonglong2 a0 = *(const ulonglong2*)(As + k * 132 + ty * 8);
            ulonglong2 a1 = *(const ulonglong2*)(As + k * 132 + ty * 8 + 4);
            float4 b0 = *(const float4*)(Bs + k * 132 + tx * 8);
            float4 b1 = *(const float4*)(Bs + k * 132 + tx * 8 + 4);
            float bv[8] = {b0.x, b0.y, b0.z, b0.w, b1.x, b1.y, b1.z, b1.w};
            uint64_t a2[4] = {a0.x, a0.y, a1.x, a1.y};
            #pragma unroll
            for (int j = 0; j < 8; j++) {
                uint64_t bs; SPLAT2(bs, bv[j]);
                FMA2(acc[0][j], a2[0], bs);
                FMA2(acc[1][j], a2[1], bs);
                FMA2(acc[2][j], a2[2], bs);
                FMA2(acc[3][j], a2[3], bs);
            }
        }
        __syncthreads();
    }

    float bb8[8];
    #pragma unroll
    for (int j = 0; j < 8; j++) bb8[j] = bias[bn * 128 + tx * 8 + j];

    const int gate = bn >> 2;
    const int jb   = (bn & 3) * 128 + tx * 8;   // j within gate

    #pragma unroll
    for (int mp = 0; mp < 4; mp++) {
        float r0[8], r1[8];
        #pragma unroll
        for (int j = 0; j < 8; j++) {
            float lo, hi; UNPK2(lo, hi, acc[mp][j]);
            r0[j] = lo + bb8[j];
            r1[j] = hi + bb8[j];
        }
        int m0 = bm * 128 + ty * 8 + mp * 2;
        float* o0 = g_xg2 + (((size_t)dir * 4 + gate) * 8192 + m0) * HDIM + jb;
        float* o1 = o0 + HDIM;
        *(float4*)(o0)     = make_float4(r0[0], r0[1], r0[2], r0[3]);
        *(float4*)(o0 + 4) = make_float4(r0[4], r0[5], r0[6], r0[7]);
        *(float4*)(o1)     = make_float4(r1[0], r1[1], r1[2], r1[3]);
        *(float4*)(o1 + 4) = make_float4(r1[4], r1[5], r1[6], r1[7]);
    }
}

// ---------------------------------------------------------------------------
// Kernel 2: persistent bidirectional LSTM recurrence, batch-split.
// 128 blocks = (dir, 32 chunks of 16 units, 2 batch halves). 256 thr.
// All-to-all flag barrier over the 32-block (dir,bh) group (1 L2 round trip).
// Cell role (u = tid&15) makes xg loads and h stores coalesced.
// ---------------------------------------------------------------------------
__global__ void __launch_bounds__(256, 1) recur_kernel(
    const float* __restrict__ whhf, const float* __restrict__ whhb)
{
    extern __shared__ float dsm[];
    float* stage = dsm;                 // 8192 floats: h[16 b][512]
    float* part  = dsm + 8192;          // (8*64)*17 + 16 floats
    __shared__ __align__(8) uint64_t mbars[4];

    const int tid = threadIdx.x;
    const int bid = blockIdx.x;
    const int dir   = bid >> 6;
    const int sub   = bid & 63;
    const int chunk = sub >> 1;         // 0..31
    const int bh    = sub & 1;          // batch half
    const int j0    = chunk * 16;       // 16 hidden units per chunk
    // GEMM role: kc = 64-wide k slice (0..7), r -> row pair {2r, 2r+1} of 64
    const int kc = tid >> 5;
    const int r  = tid & 31;
    // reduce/update role (coalesced writes): u = unit (lanes), bt = local batch
    const int u  = tid & 15;
    const int bt = tid >> 4;

    const uint32_t stage_a = smem_u32(stage);
    const uint32_t mbar_a  = smem_u32(mbars);

    if (tid == 0) {
        #pragma unroll
        for (int ch = 0; ch < 4; ch++)
            asm volatile("mbarrier.init.shared.b64 [%0], 1;" :: "r"(mbar_a + ch * 8) : "memory");
    }

    const float* whh = dir ? whhb : whhf;
    uint64_t w2[2][32];                 // 2 rows x 64 k as f32x2
    #pragma unroll
    for (int rr = 0; rr < 2; rr++) {
        int lr = 2 * r + rr;            // local row 0..63
        int grow = (lr >> 4) * HDIM + j0 + (lr & 15);
        const uint64_t* wrow = (const uint64_t*)(whh + (size_t)grow * HDIM + kc * 64);
        #pragma unroll
        for (int i = 0; i < 32; i++) w2[rr][i] = wrow[i];
    }

    float c = 0.f;                      // cell state for (dir, j0+u, bh*16+bt)

    for (int step = 0; step < SEQ; ++step) {
        const int t = dir ? (SEQ - 1 - step) : step;
        const int epoch = step + 1;

        // ---- group barrier (all-to-all over 32 blocks sharing (dir,bh)) ----
        __syncthreads();                // all h stores of this block issued
        if (tid == 0)
            asm volatile("st.release.gpu.global.s32 [%0], %1;"
                         :: "l"(g_arrive + bid), "r"(epoch) : "memory");
        if (tid < 32) {
            const int* flag = g_arrive + dir * 64 + 2 * tid + bh;
            int v;
            do {
                asm volatile("ld.acquire.gpu.global.s32 %0, [%1];"
                             : "=r"(v) : "l"(flag) : "memory");
            } while (v != epoch);
        }
        __syncthreads();

        // ---- issue 4 pipelined TMA bulk copies of h half (8KB each) ----
        const float* src = (step == 0)
            ? g_hzero + bh * 16 * HDIM
            : g_hseq + ((size_t)(dir * SEQ + (dir ? t + 1 : t - 1)) * BATCH + bh * 16) * HDIM;
        if (tid == 0) {
            asm volatile("fence.proxy.async;" ::: "memory");
            #pragma unroll
            for (int ch = 0; ch < 4; ch++) {
                asm volatile("mbarrier.arrive.expect_tx.shared.b64 _, [%0], %1;"
                             :: "r"(mbar_a + ch * 8), "r"(8192) : "memory");
                asm volatile(
                    "cp.async.bulk.shared::cluster.global.mbarrier::complete_tx::bytes "
                    "[%0], [%1], %2, [%3];"
                    :: "r"(stage_a + ch * 8192), "l"(src + ch * 2048),
                       "r"(8192), "r"(mbar_a + ch * 8) : "memory");
            }
        }

        // ---- prefetch pre-activations (coalesced along u lanes) ----
        const int m = t * 32 + bh * 16 + bt;
        float x0 = __ldg(g_xg2 + (((size_t)dir * 4 + 0) * 8192 + m) * HDIM + j0 + u);
        float x1 = __ldg(g_xg2 + (((size_t)dir * 4 + 1) * 8192 + m) * HDIM + j0 + u);
        float x2 = __ldg(g_xg2 + (((size_t)dir * 4 + 2) * 8192 + m) * HDIM + j0 + u);
        float x3 = __ldg(g_xg2 + (((size_t)dir * 4 + 3) * 8192 + m) * HDIM + j0 + u);

        // ---- GEMM, pipelined against staging chunks (4 local b per chunk) ----
        const uint32_t par = step & 1;
        #pragma unroll
        for (int ch = 0; ch < 4; ch++) {
            mbar_wait(mbar_a + ch * 8, par);
            #pragma unroll
            for (int bb = 0; bb < 4; bb++) {
                const int b = ch * 4 + bb;
                const ulonglong2* hp = (const ulonglong2*)(stage + b * HDIM + kc * 64);
                uint64_t a00 = 0ull, a01 = 0ull, a10 = 0ull, a11 = 0ull;
                #pragma unroll
                for (int i = 0; i < 16; i++) {
                    ulonglong2 h = hp[i];
                    FMA2(a00, w2[0][2 * i],     h.x);
                    FMA2(a01, w2[0][2 * i + 1], h.y);
                    FMA2(a10, w2[1][2 * i],     h.x);
                    FMA2(a11, w2[1][2 * i + 1], h.y);
                }
                float s0, s1, s2, s3;
                UNPK2(s0, s1, a00); UNPK2(s2, s3, a01);
                part[(kc * 64 + 2 * r + 0) * 17 + b] = (s0 + s1) + (s2 + s3);
                UNPK2(s0, s1, a10); UNPK2(s2, s3, a11);
                part[(kc * 64 + 2 * r + 1) * 17 + b] = (s0 + s1) + (s2 + s3);
            }
        }
        __syncthreads();

        // ---- reduce + LSTM cell for (u, bt) ----
        float gi = x0, gf = x1, gg = x2, go = x3;
        #pragma unroll
        for (int k2 = 0; k2 < 8; k2++) {
            gi += part[(k2 * 64 +  0 + u) * 17 + bt];
            gf += part[(k2 * 64 + 16 + u) * 17 + bt];
            gg += part[(k2 * 64 + 32 + u) * 17 + bt];
            go += part[(k2 * 64 + 48 + u) * 17 + bt];
        }
        float ig = 1.f / (1.f + expf(-gi));
        float fg = 1.f / (1.f + expf(-gf));
        float og = 1.f / (1.f + expf(-go));
        float gt = tanhf(gg);
        c = fg * c + ig * gt;
        float h = og * tanhf(c);

        // coalesced: lanes u consecutive
        g_hseq[((size_t)(dir * SEQ + t) * BATCH + bh * 16 + bt) * HDIM + j0 + u] = h;
    }
}

// ---------------------------------------------------------------------------
// Kernel 3: feats[s][b][tag] = [h_f | h_b] . w_out[tag] + b_out[tag]
// ---------------------------------------------------------------------------
__global__ void __launch_bounds__(256) feats_kernel(
    const float* __restrict__ w_out, const float* __restrict__ b_out)
{
    const int s = blockIdx.x;
    const int w = threadIdx.x >> 5;
    const int l = threadIdx.x & 31;

    for (int b = w; b < BATCH; b += 8) {
        const float* hf = g_hseq + ((size_t)(0 * SEQ + s) * BATCH + b) * HDIM;
        const float* hb = g_hseq + ((size_t)(1 * SEQ + s) * BATCH + b) * HDIM;
        float hv[32];
        #pragma unroll
        for (int i = 0; i < 16; i++) hv[i]      = hf[l + 32 * i];
        #pragma unroll
        for (int i = 0; i < 16; i++) hv[16 + i] = hb[l + 32 * i];
        for (int tag = 0; tag < TTAGS; tag++) {
            const float* wr = w_out + (size_t)tag * (2 * HDIM);
            float p = 0.f;
            #pragma unroll
            for (int i = 0; i < 16; i++) p = fmaf(hv[i],      wr[l + 32 * i],        p);
            #pragma unroll
            for (int i = 0; i < 16; i++) p = fmaf(hv[16 + i], wr[HDIM + l + 32 * i], p);
            #pragma unroll
            for (int o = 16; o; o >>= 1) p += __shfl_down_sync(0xffffffffu, p, o);
            if (l == 0) g_feats[(s * BATCH + b) * TTAGS + tag] = p + b_out[tag];
        }
    }
}

// ---------------------------------------------------------------------------
// Kernel 4: CRF forward. Warp per batch; smem gather for logsumexp.
// ---------------------------------------------------------------------------
__global__ void __launch_bounds__(32) crf_kernel(
    const int* __restrict__ lengths, const float* __restrict__ trans,
    float* __restrict__ out)
{
    const int b = blockIdx.x;
    const int l = threadIdx.x;

    __shared__ float fb[SEQ * TTAGS];
    __shared__ float es[32];
    for (int i = l; i < SEQ * TTAGS; i += 32) {
        int s = i / TTAGS, tg = i - s * TTAGS;
        fb[i] = g_feats[(s * BATCH + b) * TTAGS + tg];
    }

    float et[TTAGS];   // exp of transitions row for my "next" tag
    if (l < TTAGS) {
        #pragma unroll
        for (int p = 0; p < TTAGS; p++) et[p] = expf(trans[l * TTAGS + p]);
    }
    float fv = (l == START_TAG) ? 0.f : NEGV;
    es[l] = 0.f;
    __syncwarp();

    const int len = lengths[b];
    for (int s = 0; s < len; s++) {
        float v = (l < TTAGS) ? fv : -1e30f;
        #pragma unroll
        for (int o = 8; o; o >>= 1) v = fmaxf(v, __shfl_xor_sync(0xffffffffu, v, o));
        float e = (l < TTAGS) ? expf(fv - v) : 0.f;
        es[l] = e;
        __syncwarp();
        float sa = 0.f, sb = 0.f;
        #pragma unroll
        for (int p = 0; p < TTAGS; p += 2) {
            sa = fmaf(es[p],     et[p],     sa);
            sb = fmaf(es[p + 1], et[p + 1], sb);
        }
        if (l < TTAGS) fv = v + logf(sa + sb) + fb[s * TTAGS + l];
        __syncwarp();
    }

    float term = (l < TTAGS) ? (fv + trans[STOP_TAG * TTAGS + l]) : -1e30f;
    float mx = term;
    #pragma unroll
    for (int o = 16; o; o >>= 1) mx = fmaxf(mx, __shfl_xor_sync(0xffffffffu, mx, o));
    float e = (l < TTAGS) ? expf(term - mx) : 0.f;
    #pragma unroll
    for (int o = 16; o; o >>= 1) e += __shfl_xor_sync(0xffffffffu, e, o);
    if (l == 0) out[b] = (mx + logf(e)) / (float)len;
}

// ---------------------------------------------------------------------------
extern "C" void kernel_launch(void* const* d_in, const int* in_sizes, int n_in,
                              void* d_out, int out_size)
{
    const int*   tokens  = (const int*)  d_in[0];
    const int*   lengths = (const int*)  d_in[1];
    const float* emb     = (const float*)d_in[2];
    const float* w_ih_f  = (const float*)d_in[3];
    const float* w_hh_f  = (const float*)d_in[4];
    const float* b_f     = (const float*)d_in[5];
    const float* w_ih_b  = (const float*)d_in[6];
    const float* w_hh_b  = (const float*)d_in[7];
    const float* b_b     = (const float*)d_in[8];
    const float* w_out   = (const float*)d_in[9];
    const float* b_out   = (const float*)d_in[10];
    const float* trans   = (const float*)d_in[11];
    float* out = (float*)d_out;

    const int recur_smem = (8192 + 8720) * (int)sizeof(float) + 64;  // ~67.7 KB
    cudaFuncSetAttribute(recur_kernel, cudaFuncAttributeMaxDynamicSharedMemorySize, recur_smem);

    // Two dummy launches keep ncu's -s 5 -c 1 window on recur_kernel.
    dummy_kernel<<<1, 32>>>();
    dummy_kernel<<<1, 32>>>();
    xg_kernel<<<dim3(64, 16, 2), 256>>>(tokens, emb, w_ih_f, b_f, w_ih_b, b_b);
    recur_kernel<<<NBLK, 256, recur_smem>>>(w_hh_f, w_hh_b);
    feats_kernel<<<SEQ, 256>>>(w_out, b_out);
    crf_kernel<<<BATCH, 32>>>(lengths, trans, out);
}

// round 9
// speedup vs baseline: 1.6010x; 1.6010x over previous
#include <cuda_runtime.h>
#include <math.h>
#include <stdint.h>

// Problem dims (fixed)
#define SEQ 256
#define BATCH 32
#define EDIM 256
#define HDIM 512
#define GDIM 2048           // 4*H
#define TTAGS 10
#define START_TAG 8
#define STOP_TAG 9
#define NEGV -10000.0f

#define NBLK 128            // 2 dir x 32 unit-chunks x 2 batch-halves

// packed fp32x2 helpers (sm_103a native; ptxas never emits from C++)
#define FMA2(acc, a, b) asm("fma.rn.f32x2 %0, %1, %2, %3;" : "=l"(acc) : "l"(a), "l"(b), "l"(acc))
#define SPLAT2(d, s)    asm("mov.b64 %0, {%1, %1};" : "=l"(d) : "f"(s))
#define UNPK2(lo, hi, s) asm("mov.b64 {%0, %1}, %2;" : "=f"(lo), "=f"(hi) : "l"(s))

// ---------------- scratch (static device globals; no runtime alloc) ----------
// Pre-activations: [d][gate][m][j], m = t*32+b (8192), j = 0..511
__device__ float g_xg2[2u * 4 * (SEQ * BATCH) * HDIM];
__device__ float g_hseq[2u * SEQ * BATCH * HDIM];      // hidden states [d][t][b][j]
__device__ float g_hzero[BATCH * HDIM];                // never written -> stays zero
__device__ float g_feats[SEQ * BATCH * TTAGS];         // emissions
__device__ int   g_arrive[NBLK];                       // per-block arrival epochs
__device__ int   g_rel[64];                            // release words: [0]=dir0, [32]=dir1

__device__ __forceinline__ uint32_t smem_u32(const void* p) {
    uint32_t a;
    asm("{ .reg .u64 t; cvta.to.shared.u64 t, %1; cvt.u32.u64 %0, t; }" : "=r"(a) : "l"(p));
    return a;
}

__device__ __forceinline__ void mbar_wait(uint32_t addr, uint32_t par) {
    asm volatile(
        "{\n\t.reg .pred P;\n"
        "LW_%=:\n\t"
        "mbarrier.try_wait.parity.acquire.cta.shared::cta.b64 P, [%0], %1, 0x989680;\n\t"
        "@P bra LD_%=;\n\t"
        "bra LW_%=;\n"
        "LD_%=:\n\t}"
        :: "r"(addr), "r"(par) : "memory");
}

// ---------------------------------------------------------------------------
// Dummy kernels: shift the ncu capture window (-s 5 -c 1) onto recur_kernel.
// ---------------------------------------------------------------------------
__global__ void dummy_kernel() {}

// ---------------------------------------------------------------------------
// Kernel 1: xg2[d][gate][m][j] = sum_e emb[tok[m]][e] * w_ih_d[gate*512+j][e] + b
// BM=128 (m=(t,b)), BN=128, BK=16, 256 thr, 8x8 microtile (fp32x2 along m).
// ---------------------------------------------------------------------------
__global__ void __launch_bounds__(256) xg_kernel(
    const int* __restrict__ tokens, const float* __restrict__ emb,
    const float* __restrict__ wf, const float* __restrict__ bf,
    const float* __restrict__ wb, const float* __restrict__ bb)
{
    const int bm = blockIdx.x;          // 64
    const int bn = blockIdx.y;          // 16
    const int dir = blockIdx.z;         // 2
    const int tid = threadIdx.x;

    const float* w    = dir ? wb : wf;
    const float* bias = dir ? bb : bf;

    __shared__ int   rowtok[128];
    __shared__ __align__(16) float As[16 * 132];
    __shared__ __align__(16) float Bs[16 * 132];

    if (tid < 128) {
        int mg = bm * 128 + tid;                 // m = t*32 + b
        rowtok[tid] = tokens[(mg & 31) * SEQ + (mg >> 5)];
    }
    __syncthreads();

    const int ty = tid >> 4;   // 0..15 -> 8 rows (m)
    const int tx = tid & 15;   // 0..15 -> 8 cols (n)

    uint64_t acc[4][8];        // [m-pair][n], packed f32x2 along m
    #pragma unroll
    for (int i = 0; i < 4; i++)
        #pragma unroll
        for (int j = 0; j < 8; j++) acc[i][j] = 0ull;

    for (int k0 = 0; k0 < EDIM; k0 += 16) {
        #pragma unroll
        for (int it = 0; it < 2; ++it) {
            int f4 = tid + it * 256;
            int m = f4 >> 2, kq = f4 & 3;
            float4 v = *(const float4*)(emb + (size_t)rowtok[m] * EDIM + k0 + kq * 4);
            As[(kq * 4 + 0) * 132 + m] = v.x;
            As[(kq * 4 + 1) * 132 + m] = v.y;
            As[(kq * 4 + 2) * 132 + m] = v.z;
            As[(kq * 4 + 3) * 132 + m] = v.w;
        }
        #pragma unroll
        for (int it = 0; it < 2; ++it) {
            int f4 = tid + it * 256;
            int n = f4 >> 2, kq = f4 & 3;
            float4 v = *(const float4*)(w + (size_t)(bn * 128 + n) * EDIM + k0 + kq * 4);
            Bs[(kq * 4 + 0) * 132 + n] = v.x;
            Bs[(kq * 4 + 1) * 132 + n] = v.y;
            Bs[(kq * 4 + 2) * 132 + n] = v.z;
            Bs[(kq * 4 + 3) * 132 + n] = v.w;
        }
        __syncthreads();
        #pragma unroll
        for (int k = 0; k < 16; k++) {
            ulonglong2 a0 = *(const ulonglong2*)(As + k * 132 + ty * 8);
            ulonglong2 a1 = *(const ulonglong2*)(As + k * 132 + ty * 8 + 4);
            float4 b0 = *(const float4*)(Bs + k * 132 + tx * 8);
            float4 b1 = *(const float4*)(Bs + k * 132 + tx * 8 + 4);
            float bv[8] = {b0.x, b0.y, b0.z, b0.w, b1.x, b1.y, b1.z, b1.w};
            uint64_t a2[4] = {a0.x, a0.y, a1.x, a1.y};
            #pragma unroll
            for (int j = 0; j < 8; j++) {
                uint64_t bs; SPLAT2(bs, bv[j]);
                FMA2(acc[0][j], a2[0], bs);
                FMA2(acc[1][j], a2[1], bs);
                FMA2(acc[2][j], a2[2], bs);
                FMA2(acc[3][j], a2[3], bs);
            }
        }
        __syncthreads();
    }

    float bb8[8];
    #pragma unroll
    for (int j = 0; j < 8; j++) bb8[j] = bias[bn * 128 + tx * 8 + j];

    const int gate = bn >> 2;
    const int jb   = (bn & 3) * 128 + tx * 8;   // j within gate

    #pragma unroll
    for (int mp = 0; mp < 4; mp++) {
        float r0[8], r1[8];
        #pragma unroll
        for (int j = 0; j < 8; j++) {
            float lo, hi; UNPK2(lo, hi, acc[mp][j]);
            r0[j] = lo + bb8[j];
            r1[j] = hi + bb8[j];
        }
        int m0 = bm * 128 + ty * 8 + mp * 2;
        float* o0 = g_xg2 + (((size_t)dir * 4 + gate) * 8192 + m0) * HDIM + jb;
        float* o1 = o0 + HDIM;
        *(float4*)(o0)     = make_float4(r0[0], r0[1], r0[2], r0[3]);
        *(float4*)(o0 + 4) = make_float4(r0[4], r0[5], r0[6], r0[7]);
        *(float4*)(o1)     = make_float4(r1[0], r1[1], r1[2], r1[3]);
        *(float4*)(o1 + 4) = make_float4(r1[4], r1[5], r1[6], r1[7]);
    }
}

// ---------------------------------------------------------------------------
// Kernel 2: persistent bidirectional LSTM recurrence, batch-split.
// 128 blocks = (dir, 32 chunks of 16 units, 2 batch halves). 256 thr.
// Master-relay barrier per direction (same-address release polling -> LTS
// broadcast friendly; the R7 all-to-all distinct-address poll serialized).
// ---------------------------------------------------------------------------
__global__ void __launch_bounds__(256, 1) recur_kernel(
    const float* __restrict__ whhf, const float* __restrict__ whhb)
{
    extern __shared__ float dsm[];
    float* stage = dsm;                 // 8192 floats: h[16 b][512]
    float* part  = dsm + 8192;          // (8*64)*17 + 16 floats
    __shared__ __align__(8) uint64_t mbars[4];

    const int tid = threadIdx.x;
    const int bid = blockIdx.x;
    const int dir   = bid >> 6;
    const int sub   = bid & 63;
    const int chunk = sub >> 1;         // 0..31
    const int bh    = sub & 1;          // batch half
    const int j0    = chunk * 16;       // 16 hidden units per chunk
    // GEMM role: kc = 64-wide k slice (0..7), r -> row pair {2r, 2r+1} of 64
    const int kc = tid >> 5;
    const int r  = tid & 31;
    // reduce/update role (coalesced writes): u = unit (lanes), bt = local batch
    const int u  = tid & 15;
    const int bt = tid >> 4;

    const uint32_t stage_a = smem_u32(stage);
    const uint32_t mbar_a  = smem_u32(mbars);

    if (tid == 0) {
        #pragma unroll
        for (int ch = 0; ch < 4; ch++)
            asm volatile("mbarrier.init.shared.b64 [%0], 1;" :: "r"(mbar_a + ch * 8) : "memory");
    }

    const float* whh = dir ? whhb : whhf;
    uint64_t w2[2][32];                 // 2 rows x 64 k as f32x2
    #pragma unroll
    for (int rr = 0; rr < 2; rr++) {
        int lr = 2 * r + rr;            // local row 0..63
        int grow = (lr >> 4) * HDIM + j0 + (lr & 15);
        const uint64_t* wrow = (const uint64_t*)(whh + (size_t)grow * HDIM + kc * 64);
        #pragma unroll
        for (int i = 0; i < 32; i++) w2[rr][i] = wrow[i];
    }

    float c = 0.f;                      // cell state for (dir, j0+u, bh*16+bt)
    const bool master = (sub == 0);

    for (int step = 0; step < SEQ; ++step) {
        const int t = dir ? (SEQ - 1 - step) : step;
        const int epoch = step + 1;

        // ---- grid barrier: publish h(step-1), wait for whole direction ----
        __syncthreads();
        if (tid == 0)
            asm volatile("st.release.gpu.global.s32 [%0], %1;"
                         :: "l"(g_arrive + bid), "r"(epoch) : "memory");
        if (master) {
            if (tid < 64) {
                int v;
                do {
                    asm volatile("ld.acquire.gpu.global.s32 %0, [%1];"
                                 : "=r"(v) : "l"(g_arrive + dir * 64 + tid) : "memory");
                } while (v != epoch);
            }
            __syncthreads();
            if (tid == 0)
                asm volatile("st.release.gpu.global.s32 [%0], %1;"
                             :: "l"(g_rel + dir * 32), "r"(epoch) : "memory");
        } else {
            if (tid == 0) {
                int v;
                do {
                    asm volatile("ld.acquire.gpu.global.s32 %0, [%1];"
                                 : "=r"(v) : "l"(g_rel + dir * 32) : "memory");
                } while (v != epoch);
            }
            __syncthreads();
        }

        // ---- issue 4 pipelined TMA bulk copies of h half (8KB each) ----
        const float* src = (step == 0)
            ? g_hzero + bh * 16 * HDIM
            : g_hseq + ((size_t)(dir * SEQ + (dir ? t + 1 : t - 1)) * BATCH + bh * 16) * HDIM;
        if (tid == 0) {
            asm volatile("fence.proxy.async;" ::: "memory");
            #pragma unroll
            for (int ch = 0; ch < 4; ch++) {
                asm volatile("mbarrier.arrive.expect_tx.shared.b64 _, [%0], %1;"
                             :: "r"(mbar_a + ch * 8), "r"(8192) : "memory");
                asm volatile(
                    "cp.async.bulk.shared::cluster.global.mbarrier::complete_tx::bytes "
                    "[%0], [%1], %2, [%3];"
                    :: "r"(stage_a + ch * 8192), "l"(src + ch * 2048),
                       "r"(8192), "r"(mbar_a + ch * 8) : "memory");
            }
        }

        // ---- prefetch pre-activations (coalesced along u lanes) ----
        const int m = t * 32 + bh * 16 + bt;
        float x0 = __ldg(g_xg2 + (((size_t)dir * 4 + 0) * 8192 + m) * HDIM + j0 + u);
        float x1 = __ldg(g_xg2 + (((size_t)dir * 4 + 1) * 8192 + m) * HDIM + j0 + u);
        float x2 = __ldg(g_xg2 + (((size_t)dir * 4 + 2) * 8192 + m) * HDIM + j0 + u);
        float x3 = __ldg(g_xg2 + (((size_t)dir * 4 + 3) * 8192 + m) * HDIM + j0 + u);

        // ---- GEMM, pipelined against staging chunks (4 local b per chunk) ----
        const uint32_t par = step & 1;
        #pragma unroll
        for (int ch = 0; ch < 4; ch++) {
            mbar_wait(mbar_a + ch * 8, par);
            #pragma unroll
            for (int bb = 0; bb < 4; bb++) {
                const int b = ch * 4 + bb;
                const ulonglong2* hp = (const ulonglong2*)(stage + b * HDIM + kc * 64);
                uint64_t a00 = 0ull, a01 = 0ull, a10 = 0ull, a11 = 0ull;
                #pragma unroll
                for (int i = 0; i < 16; i++) {
                    ulonglong2 h = hp[i];
                    FMA2(a00, w2[0][2 * i],     h.x);
                    FMA2(a01, w2[0][2 * i + 1], h.y);
                    FMA2(a10, w2[1][2 * i],     h.x);
                    FMA2(a11, w2[1][2 * i + 1], h.y);
                }
                float s0, s1, s2, s3;
                UNPK2(s0, s1, a00); UNPK2(s2, s3, a01);
                part[(kc * 64 + 2 * r + 0) * 17 + b] = (s0 + s1) + (s2 + s3);
                UNPK2(s0, s1, a10); UNPK2(s2, s3, a11);
                part[(kc * 64 + 2 * r + 1) * 17 + b] = (s0 + s1) + (s2 + s3);
            }
        }
        __syncthreads();

        // ---- reduce + LSTM cell for (u, bt) ----
        float gi = x0, gf = x1, gg = x2, go = x3;
        #pragma unroll
        for (int k2 = 0; k2 < 8; k2++) {
            gi += part[(k2 * 64 +  0 + u) * 17 + bt];
            gf += part[(k2 * 64 + 16 + u) * 17 + bt];
            gg += part[(k2 * 64 + 32 + u) * 17 + bt];
            go += part[(k2 * 64 + 48 + u) * 17 + bt];
        }
        float ig = 1.f / (1.f + expf(-gi));
        float fg = 1.f / (1.f + expf(-gf));
        float og = 1.f / (1.f + expf(-go));
        float gt = tanhf(gg);
        c = fg * c + ig * gt;
        float h = og * tanhf(c);

        // coalesced: lanes u consecutive
        g_hseq[((size_t)(dir * SEQ + t) * BATCH + bh * 16 + bt) * HDIM + j0 + u] = h;
    }
}

// ---------------------------------------------------------------------------
// Kernel 3: feats[s][b][tag] = [h_f | h_b] . w_out[tag] + b_out[tag]
// ---------------------------------------------------------------------------
__global__ void __launch_bounds__(256) feats_kernel(
    const float* __restrict__ w_out, const float* __restrict__ b_out)
{
    const int s = blockIdx.x;
    const int w = threadIdx.x >> 5;
    const int l = threadIdx.x & 31;

    for (int b = w; b < BATCH; b += 8) {
        const float* hf = g_hseq + ((size_t)(0 * SEQ + s) * BATCH + b) * HDIM;
        const float* hb = g_hseq + ((size_t)(1 * SEQ + s) * BATCH + b) * HDIM;
        float hv[32];
        #pragma unroll
        for (int i = 0; i < 16; i++) hv[i]      = hf[l + 32 * i];
        #pragma unroll
        for (int i = 0; i < 16; i++) hv[16 + i] = hb[l + 32 * i];
        for (int tag = 0; tag < TTAGS; tag++) {
            const float* wr = w_out + (size_t)tag * (2 * HDIM);
            float p = 0.f;
            #pragma unroll
            for (int i = 0; i < 16; i++) p = fmaf(hv[i],      wr[l + 32 * i],        p);
            #pragma unroll
            for (int i = 0; i < 16; i++) p = fmaf(hv[16 + i], wr[HDIM + l + 32 * i], p);
            #pragma unroll
            for (int o = 16; o; o >>= 1) p += __shfl_down_sync(0xffffffffu, p, o);
            if (l == 0) g_feats[(s * BATCH + b) * TTAGS + tag] = p + b_out[tag];
        }
    }
}

// ---------------------------------------------------------------------------
// Kernel 4: CRF forward. Warp per batch; smem gather for logsumexp.
// ---------------------------------------------------------------------------
__global__ void __launch_bounds__(32) crf_kernel(
    const int* __restrict__ lengths, const float* __restrict__ trans,
    float* __restrict__ out)
{
    const int b = blockIdx.x;
    const int l = threadIdx.x;

    __shared__ float fb[SEQ * TTAGS];
    __shared__ float es[32];
    for (int i = l; i < SEQ * TTAGS; i += 32) {
        int s = i / TTAGS, tg = i - s * TTAGS;
        fb[i] = g_feats[(s * BATCH + b) * TTAGS + tg];
    }

    float et[TTAGS];   // exp of transitions row for my "next" tag
    if (l < TTAGS) {
        #pragma unroll
        for (int p = 0; p < TTAGS; p++) et[p] = expf(trans[l * TTAGS + p]);
    }
    float fv = (l == START_TAG) ? 0.f : NEGV;
    es[l] = 0.f;
    __syncwarp();

    const int len = lengths[b];
    for (int s = 0; s < len; s++) {
        float v = (l < TTAGS) ? fv : -1e30f;
        #pragma unroll
        for (int o = 8; o; o >>= 1) v = fmaxf(v, __shfl_xor_sync(0xffffffffu, v, o));
        float e = (l < TTAGS) ? expf(fv - v) : 0.f;
        es[l] = e;
        __syncwarp();
        float sa = 0.f, sb = 0.f;
        #pragma unroll
        for (int p = 0; p < TTAGS; p += 2) {
            sa = fmaf(es[p],     et[p],     sa);
            sb = fmaf(es[p + 1], et[p + 1], sb);
        }
        if (l < TTAGS) fv = v + logf(sa + sb) + fb[s * TTAGS + l];
        __syncwarp();
    }

    float term = (l < TTAGS) ? (fv + trans[STOP_TAG * TTAGS + l]) : -1e30f;
    float mx = term;
    #pragma unroll
    for (int o = 16; o; o >>= 1) mx = fmaxf(mx, __shfl_xor_sync(0xffffffffu, mx, o));
    float e = (l < TTAGS) ? expf(term - mx) : 0.f;
    #pragma unroll
    for (int o = 16; o; o >>= 1) e += __shfl_xor_sync(0xffffffffu, e, o);
    if (l == 0) out[b] = (mx + logf(e)) / (float)len;
}

// ---------------------------------------------------------------------------
extern "C" void kernel_launch(void* const* d_in, const int* in_sizes, int n_in,
                              void* d_out, int out_size)
{
    const int*   tokens  = (const int*)  d_in[0];
    const int*   lengths = (const int*)  d_in[1];
    const float* emb     = (const float*)d_in[2];
    const float* w_ih_f  = (const float*)d_in[3];
    const float* w_hh_f  = (const float*)d_in[4];
    const float* b_f     = (const float*)d_in[5];
    const float* w_ih_b  = (const float*)d_in[6];
    const float* w_hh_b  = (const float*)d_in[7];
    const float* b_b     = (const float*)d_in[8];
    const float* w_out   = (const float*)d_in[9];
    const float* b_out   = (const float*)d_in[10];
    const float* trans   = (const float*)d_in[11];
    float* out = (float*)d_out;

    const int recur_smem = (8192 + 8720) * (int)sizeof(float) + 64;  // ~67.7 KB
    cudaFuncSetAttribute(recur_kernel, cudaFuncAttributeMaxDynamicSharedMemorySize, recur_smem);

    // Two dummy launches keep ncu's -s 5 -c 1 window on recur_kernel.
    dummy_kernel<<<1, 32>>>();
    dummy_kernel<<<1, 32>>>();
    xg_kernel<<<dim3(64, 16, 2), 256>>>(tokens, emb, w_ih_f, b_f, w_ih_b, b_b);
    recur_kernel<<<NBLK, 256, recur_smem>>>(w_hh_f, w_hh_b);
    feats_kernel<<<SEQ, 256>>>(w_out, b_out);
    crf_kernel<<<BATCH, 32>>>(lengths, trans, out);
}

// round 10
// speedup vs baseline: 1.7872x; 1.1163x over previous
#include <cuda_runtime.h>
#include <math.h>
#include <stdint.h>

// Problem dims (fixed)
#define SEQ 256
#define BATCH 32
#define EDIM 256
#define HDIM 512
#define GDIM 2048           // 4*H
#define TTAGS 10
#define START_TAG 8
#define STOP_TAG 9
#define NEGV -10000.0f

#define NBLK 128            // 2 dir x 32 unit-chunks x 2 batch-halves

// packed fp32x2 helpers (sm_103a native; ptxas never emits from C++)
#define FMA2(acc, a, b) asm("fma.rn.f32x2 %0, %1, %2, %3;" : "=l"(acc) : "l"(a), "l"(b), "l"(acc))
#define SPLAT2(d, s)    asm("mov.b64 %0, {%1, %1};" : "=l"(d) : "f"(s))
#define UNPK2(lo, hi, s) asm("mov.b64 {%0, %1}, %2;" : "=f"(lo), "=f"(hi) : "l"(s))

// fast activations (MUFU-based; |err| ~1e-6, budget 1e-3)
__device__ __forceinline__ float fsig(float x)  { return 1.f / (1.f + __expf(-x)); }
__device__ __forceinline__ float ftanh(float x) { return 1.f - 2.f / (__expf(2.f * x) + 1.f); }

// ---------------- scratch (static device globals; no runtime alloc) ----------
// Pre-activations: [d][gate][m][j], m = t*32+b (8192), j = 0..511
__device__ float g_xg2[2u * 4 * (SEQ * BATCH) * HDIM];
__device__ float g_hseq[2u * SEQ * BATCH * HDIM];      // hidden states [d][t][b][j]
__device__ float g_hzero[BATCH * HDIM];                // never written -> stays zero
__device__ float g_feats[SEQ * BATCH * TTAGS];         // emissions
__device__ int   g_cnt[4 * 32];                        // group counters at [g*32]

__device__ __forceinline__ uint32_t smem_u32(const void* p) {
    uint32_t a;
    asm("{ .reg .u64 t; cvta.to.shared.u64 t, %1; cvt.u32.u64 %0, t; }" : "=r"(a) : "l"(p));
    return a;
}

__device__ __forceinline__ void mbar_wait(uint32_t addr, uint32_t par) {
    asm volatile(
        "{\n\t.reg .pred P;\n"
        "LW_%=:\n\t"
        "mbarrier.try_wait.parity.acquire.cta.shared::cta.b64 P, [%0], %1, 0x989680;\n\t"
        "@P bra LD_%=;\n\t"
        "bra LW_%=;\n"
        "LD_%=:\n\t}"
        :: "r"(addr), "r"(par) : "memory");
}

// ---------------------------------------------------------------------------
// Dummy kernels: shift the ncu capture window (-s 5 -c 1) onto recur_kernel.
// ---------------------------------------------------------------------------
__global__ void dummy_kernel() {}

// ---------------------------------------------------------------------------
// Kernel 1: xg2[d][gate][m][j] = sum_e emb[tok[m]][e] * w_ih_d[gate*512+j][e] + b
// BM=128 (m=(t,b)), BN=128, BK=16, 256 thr, 8x8 microtile (fp32x2 along m).
// Also resets the recurrence barrier counters (runs before recur each launch).
// ---------------------------------------------------------------------------
__global__ void __launch_bounds__(256) xg_kernel(
    const int* __restrict__ tokens, const float* __restrict__ emb,
    const float* __restrict__ wf, const float* __restrict__ bf,
    const float* __restrict__ wb, const float* __restrict__ bb)
{
    const int bm = blockIdx.x;          // 64
    const int bn = blockIdx.y;          // 16
    const int dir = blockIdx.z;         // 2
    const int tid = threadIdx.x;

    if (bm == 0 && bn == 0 && dir == 0 && tid < 4) g_cnt[tid * 32] = 0;

    const float* w    = dir ? wb : wf;
    const float* bias = dir ? bb : bf;

    __shared__ int   rowtok[128];
    __shared__ __align__(16) float As[16 * 132];
    __shared__ __align__(16) float Bs[16 * 132];

    if (tid < 128) {
        int mg = bm * 128 + tid;                 // m = t*32 + b
        rowtok[tid] = tokens[(mg & 31) * SEQ + (mg >> 5)];
    }
    __syncthreads();

    const int ty = tid >> 4;   // 0..15 -> 8 rows (m)
    const int tx = tid & 15;   // 0..15 -> 8 cols (n)

    uint64_t acc[4][8];        // [m-pair][n], packed f32x2 along m
    #pragma unroll
    for (int i = 0; i < 4; i++)
        #pragma unroll
        for (int j = 0; j < 8; j++) acc[i][j] = 0ull;

    for (int k0 = 0; k0 < EDIM; k0 += 16) {
        #pragma unroll
        for (int it = 0; it < 2; ++it) {
            int f4 = tid + it * 256;
            int m = f4 >> 2, kq = f4 & 3;
            float4 v = *(const float4*)(emb + (size_t)rowtok[m] * EDIM + k0 + kq * 4);
            As[(kq * 4 + 0) * 132 + m] = v.x;
            As[(kq * 4 + 1) * 132 + m] = v.y;
            As[(kq * 4 + 2) * 132 + m] = v.z;
            As[(kq * 4 + 3) * 132 + m] = v.w;
        }
        #pragma unroll
        for (int it = 0; it < 2; ++it) {
            int f4 = tid + it * 256;
            int n = f4 >> 2, kq = f4 & 3;
            float4 v = *(const float4*)(w + (size_t)(bn * 128 + n) * EDIM + k0 + kq * 4);
            Bs[(kq * 4 + 0) * 132 + n] = v.x;
            Bs[(kq * 4 + 1) * 132 + n] = v.y;
            Bs[(kq * 4 + 2) * 132 + n] = v.z;
            Bs[(kq * 4 + 3) * 132 + n] = v.w;
        }
        __syncthreads();
        #pragma unroll
        for (int k = 0; k < 16; k++) {
            ulonglong2 a0 = *(const ulonglong2*)(As + k * 132 + ty * 8);
            ulonglong2 a1 = *(const ulonglong2*)(As + k * 132 + ty * 8 + 4);
            float4 b0 = *(const float4*)(Bs + k * 132 + tx * 8);
            float4 b1 = *(const float4*)(Bs + k * 132 + tx * 8 + 4);
            float bv[8] = {b0.x, b0.y, b0.z, b0.w, b1.x, b1.y, b1.z, b1.w};
            uint64_t a2[4] = {a0.x, a0.y, a1.x, a1.y};
            #pragma unroll
            for (int j = 0; j < 8; j++) {
                uint64_t bs; SPLAT2(bs, bv[j]);
                FMA2(acc[0][j], a2[0], bs);
                FMA2(acc[1][j], a2[1], bs);
                FMA2(acc[2][j], a2[2], bs);
                FMA2(acc[3][j], a2[3], bs);
            }
        }
        __syncthreads();
    }

    float bb8[8];
    #pragma unroll
    for (int j = 0; j < 8; j++) bb8[j] = bias[bn * 128 + tx * 8 + j];

    const int gate = bn >> 2;
    const int jb   = (bn & 3) * 128 + tx * 8;   // j within gate

    #pragma unroll
    for (int mp = 0; mp < 4; mp++) {
        float r0[8], r1[8];
        #pragma unroll
        for (int j = 0; j < 8; j++) {
            float lo, hi; UNPK2(lo, hi, acc[mp][j]);
            r0[j] = lo + bb8[j];
            r1[j] = hi + bb8[j];
        }
        int m0 = bm * 128 + ty * 8 + mp * 2;
        float* o0 = g_xg2 + (((size_t)dir * 4 + gate) * 8192 + m0) * HDIM + jb;
        float* o1 = o0 + HDIM;
        *(float4*)(o0)     = make_float4(r0[0], r0[1], r0[2], r0[3]);
        *(float4*)(o0 + 4) = make_float4(r0[4], r0[5], r0[6], r0[7]);
        *(float4*)(o1)     = make_float4(r1[0], r1[1], r1[2], r1[3]);
        *(float4*)(o1 + 4) = make_float4(r1[4], r1[5], r1[6], r1[7]);
    }
}

// ---------------------------------------------------------------------------
// Kernel 2: persistent bidirectional LSTM recurrence, batch-split.
// 128 blocks = (dir, 32 chunks of 16 units, 2 batch halves). 256 thr.
// Barrier: one REDG counter per (dir,bh) group of 32 blocks — single L2
// round trip (fire-and-forget arrive + same-address acquire polling).
// tid0 chains poll -> fence -> TMA issue; no second __syncthreads.
// ---------------------------------------------------------------------------
__global__ void __launch_bounds__(256, 1) recur_kernel(
    const float* __restrict__ whhf, const float* __restrict__ whhb)
{
    extern __shared__ float dsm[];
    float* stage = dsm;                 // 8192 floats: h[16 b][512]
    float* part  = dsm + 8192;          // (8*64)*17 + 16 floats
    __shared__ __align__(8) uint64_t mbars[4];

    const int tid = threadIdx.x;
    const int bid = blockIdx.x;
    const int dir   = bid >> 6;
    const int sub   = bid & 63;
    const int chunk = sub >> 1;         // 0..31
    const int bh    = sub & 1;          // batch half
    const int j0    = chunk * 16;       // 16 hidden units per chunk
    // GEMM role: kc = 64-wide k slice (0..7), r -> row pair {2r, 2r+1} of 64
    const int kc = tid >> 5;
    const int r  = tid & 31;
    // reduce/update role (coalesced writes): u = unit (lanes), bt = local batch
    const int u  = tid & 15;
    const int bt = tid >> 4;

    int* cnt = g_cnt + (dir * 2 + bh) * 32;   // group counter (32 arrivals/epoch)

    const uint32_t stage_a = smem_u32(stage);
    const uint32_t mbar_a  = smem_u32(mbars);

    if (tid == 0) {
        #pragma unroll
        for (int ch = 0; ch < 4; ch++)
            asm volatile("mbarrier.init.shared.b64 [%0], 1;" :: "r"(mbar_a + ch * 8) : "memory");
    }

    const float* whh = dir ? whhb : whhf;
    uint64_t w2[2][32];                 // 2 rows x 64 k as f32x2
    #pragma unroll
    for (int rr = 0; rr < 2; rr++) {
        int lr = 2 * r + rr;            // local row 0..63
        int grow = (lr >> 4) * HDIM + j0 + (lr & 15);
        const uint64_t* wrow = (const uint64_t*)(whh + (size_t)grow * HDIM + kc * 64);
        #pragma unroll
        for (int i = 0; i < 32; i++) w2[rr][i] = wrow[i];
    }

    float c = 0.f;                      // cell state for (dir, j0+u, bh*16+bt)

    for (int step = 0; step < SEQ; ++step) {
        const int t = dir ? (SEQ - 1 - step) : step;
        const int target = 32 * (step + 1);

        // ---- group barrier: REDG arrive + same-address poll (1 round trip) ----
        __syncthreads();                // all h stores of this block issued
        if (tid == 0) {
            asm volatile("red.release.gpu.global.add.s32 [%0], %1;"
                         :: "l"(cnt), "r"(1) : "memory");
            int v;
            do {
                asm volatile("ld.acquire.gpu.global.s32 %0, [%1];"
                             : "=r"(v) : "l"(cnt) : "memory");
            } while (v < target);
            // ---- issue 4 pipelined TMA bulk copies of h half (8KB each) ----
            const float* src = (step == 0)
                ? g_hzero + bh * 16 * HDIM
                : g_hseq + ((size_t)(dir * SEQ + (dir ? t + 1 : t - 1)) * BATCH + bh * 16) * HDIM;
            asm volatile("fence.proxy.async;" ::: "memory");
            #pragma unroll
            for (int ch = 0; ch < 4; ch++) {
                asm volatile("mbarrier.arrive.expect_tx.shared.b64 _, [%0], %1;"
                             :: "r"(mbar_a + ch * 8), "r"(8192) : "memory");
                asm volatile(
                    "cp.async.bulk.shared::cluster.global.mbarrier::complete_tx::bytes "
                    "[%0], [%1], %2, [%3];"
                    :: "r"(stage_a + ch * 8192), "l"(src + ch * 2048),
                       "r"(8192), "r"(mbar_a + ch * 8) : "memory");
            }
        }

        // ---- prefetch pre-activations (independent of h; issues while tid0 polls)
        const int m = t * 32 + bh * 16 + bt;
        float x0 = __ldg(g_xg2 + (((size_t)dir * 4 + 0) * 8192 + m) * HDIM + j0 + u);
        float x1 = __ldg(g_xg2 + (((size_t)dir * 4 + 1) * 8192 + m) * HDIM + j0 + u);
        float x2 = __ldg(g_xg2 + (((size_t)dir * 4 + 2) * 8192 + m) * HDIM + j0 + u);
        float x3 = __ldg(g_xg2 + (((size_t)dir * 4 + 3) * 8192 + m) * HDIM + j0 + u);

        // ---- GEMM, pipelined against staging chunks (4 local b per chunk) ----
        const uint32_t par = step & 1;
        #pragma unroll
        for (int ch = 0; ch < 4; ch++) {
            mbar_wait(mbar_a + ch * 8, par);
            #pragma unroll
            for (int bb = 0; bb < 4; bb++) {
                const int b = ch * 4 + bb;
                const ulonglong2* hp = (const ulonglong2*)(stage + b * HDIM + kc * 64);
                uint64_t a00 = 0ull, a01 = 0ull, a10 = 0ull, a11 = 0ull;
                #pragma unroll
                for (int i = 0; i < 16; i++) {
                    ulonglong2 h = hp[i];
                    FMA2(a00, w2[0][2 * i],     h.x);
                    FMA2(a01, w2[0][2 * i + 1], h.y);
                    FMA2(a10, w2[1][2 * i],     h.x);
                    FMA2(a11, w2[1][2 * i + 1], h.y);
                }
                float s0, s1, s2, s3;
                UNPK2(s0, s1, a00); UNPK2(s2, s3, a01);
                part[(kc * 64 + 2 * r + 0) * 17 + b] = (s0 + s1) + (s2 + s3);
                UNPK2(s0, s1, a10); UNPK2(s2, s3, a11);
                part[(kc * 64 + 2 * r + 1) * 17 + b] = (s0 + s1) + (s2 + s3);
            }
        }
        __syncthreads();

        // ---- reduce + LSTM cell for (u, bt) ----
        float gi = x0, gf = x1, gg = x2, go = x3;
        #pragma unroll
        for (int k2 = 0; k2 < 8; k2++) {
            gi += part[(k2 * 64 +  0 + u) * 17 + bt];
            gf += part[(k2 * 64 + 16 + u) * 17 + bt];
            gg += part[(k2 * 64 + 32 + u) * 17 + bt];
            go += part[(k2 * 64 + 48 + u) * 17 + bt];
        }
        float ig = fsig(gi);
        float fg = fsig(gf);
        float og = fsig(go);
        float gt = ftanh(gg);
        c = fg * c + ig * gt;
        float h = og * ftanh(c);

        // coalesced: lanes u consecutive
        g_hseq[((size_t)(dir * SEQ + t) * BATCH + bh * 16 + bt) * HDIM + j0 + u] = h;
    }
}

// ---------------------------------------------------------------------------
// Kernel 3: feats[s][b][tag] = [h_f | h_b] . w_out[tag] + b_out[tag]
// ---------------------------------------------------------------------------
__global__ void __launch_bounds__(256) feats_kernel(
    const float* __restrict__ w_out, const float* __restrict__ b_out)
{
    const int s = blockIdx.x;
    const int w = threadIdx.x >> 5;
    const int l = threadIdx.x & 31;

    for (int b = w; b < BATCH; b += 8) {
        const float* hf = g_hseq + ((size_t)(0 * SEQ + s) * BATCH + b) * HDIM;
        const float* hb = g_hseq + ((size_t)(1 * SEQ + s) * BATCH + b) * HDIM;
        float hv[32];
        #pragma unroll
        for (int i = 0; i < 16; i++) hv[i]      = hf[l + 32 * i];
        #pragma unroll
        for (int i = 0; i < 16; i++) hv[16 + i] = hb[l + 32 * i];
        for (int tag = 0; tag < TTAGS; tag++) {
            const float* wr = w_out + (size_t)tag * (2 * HDIM);
            float p = 0.f;
            #pragma unroll
            for (int i = 0; i < 16; i++) p = fmaf(hv[i],      wr[l + 32 * i],        p);
            #pragma unroll
            for (int i = 0; i < 16; i++) p = fmaf(hv[16 + i], wr[HDIM + l + 32 * i], p);
            #pragma unroll
            for (int o = 16; o; o >>= 1) p += __shfl_down_sync(0xffffffffu, p, o);
            if (l == 0) g_feats[(s * BATCH + b) * TTAGS + tag] = p + b_out[tag];
        }
    }
}

// ---------------------------------------------------------------------------
// Kernel 4: CRF forward. Warp per batch; smem gather for logsumexp.
// ---------------------------------------------------------------------------
__global__ void __launch_bounds__(32) crf_kernel(
    const int* __restrict__ lengths, const float* __restrict__ trans,
    float* __restrict__ out)
{
    const int b = blockIdx.x;
    const int l = threadIdx.x;

    __shared__ float fb[SEQ * TTAGS];
    __shared__ float es[32];
    for (int i = l; i < SEQ * TTAGS; i += 32) {
        int s = i / TTAGS, tg = i - s * TTAGS;
        fb[i] = g_feats[(s * BATCH + b) * TTAGS + tg];
    }

    float et[TTAGS];   // exp of transitions row for my "next" tag
    if (l < TTAGS) {
        #pragma unroll
        for (int p = 0; p < TTAGS; p++) et[p] = expf(trans[l * TTAGS + p]);
    }
    float fv = (l == START_TAG) ? 0.f : NEGV;
    es[l] = 0.f;
    __syncwarp();

    const int len = lengths[b];
    for (int s = 0; s < len; s++) {
        float v = (l < TTAGS) ? fv : -1e30f;
        #pragma unroll
        for (int o = 8; o; o >>= 1) v = fmaxf(v, __shfl_xor_sync(0xffffffffu, v, o));
        float e = (l < TTAGS) ? expf(fv - v) : 0.f;
        es[l] = e;
        __syncwarp();
        float sa = 0.f, sb = 0.f;
        #pragma unroll
        for (int p = 0; p < TTAGS; p += 2) {
            sa = fmaf(es[p],     et[p],     sa);
            sb = fmaf(es[p + 1], et[p + 1], sb);
        }
        if (l < TTAGS) fv = v + logf(sa + sb) + fb[s * TTAGS + l];
        __syncwarp();
    }

    float term = (l < TTAGS) ? (fv + trans[STOP_TAG * TTAGS + l]) : -1e30f;
    float mx = term;
    #pragma unroll
    for (int o = 16; o; o >>= 1) mx = fmaxf(mx, __shfl_xor_sync(0xffffffffu, mx, o));
    float e = (l < TTAGS) ? expf(term - mx) : 0.f;
    #pragma unroll
    for (int o = 16; o; o >>= 1) e += __shfl_xor_sync(0xffffffffu, e, o);
    if (l == 0) out[b] = (mx + logf(e)) / (float)len;
}

// ---------------------------------------------------------------------------
extern "C" void kernel_launch(void* const* d_in, const int* in_sizes, int n_in,
                              void* d_out, int out_size)
{
    const int*   tokens  = (const int*)  d_in[0];
    const int*   lengths = (const int*)  d_in[1];
    const float* emb     = (const float*)d_in[2];
    const float* w_ih_f  = (const float*)d_in[3];
    const float* w_hh_f  = (const float*)d_in[4];
    const float* b_f     = (const float*)d_in[5];
    const float* w_ih_b  = (const float*)d_in[6];
    const float* w_hh_b  = (const float*)d_in[7];
    const float* b_b     = (const float*)d_in[8];
    const float* w_out   = (const float*)d_in[9];
    const float* b_out   = (const float*)d_in[10];
    const float* trans   = (const float*)d_in[11];
    float* out = (float*)d_out;

    const int recur_smem = (8192 + 8720) * (int)sizeof(float) + 64;  // ~67.7 KB
    cudaFuncSetAttribute(recur_kernel, cudaFuncAttributeMaxDynamicSharedMemorySize, recur_smem);

    // Two dummy launches keep ncu's -s 5 -c 1 window on recur_kernel.
    dummy_kernel<<<1, 32>>>();
    dummy_kernel<<<1, 32>>>();
    xg_kernel<<<dim3(64, 16, 2), 256>>>(tokens, emb, w_ih_f, b_f, w_ih_b, b_b);
    recur_kernel<<<NBLK, 256, recur_smem>>>(w_hh_f, w_hh_b);
    feats_kernel<<<SEQ, 256>>>(w_out, b_out);
    crf_kernel<<<BATCH, 32>>>(lengths, trans, out);
}

// round 12
// speedup vs baseline: 2.5706x; 1.4383x over previous
#include <cuda_runtime.h>
#include <cuda_bf16.h>
#include <math.h>
#include <stdint.h>

// Problem dims (fixed)
#define SEQ 256
#define BATCH 32
#define EDIM 256
#define HDIM 512
#define GDIM 2048           // 4*H
#define TTAGS 10
#define START_TAG 8
#define STOP_TAG 9
#define NEGV -10000.0f

// packed fp32x2 helpers (xg kernel)
#define FMA2(acc, a, b) asm("fma.rn.f32x2 %0, %1, %2, %3;" : "=l"(acc) : "l"(a), "l"(b), "l"(acc))
#define SPLAT2(d, s)    asm("mov.b64 %0, {%1, %1};" : "=l"(d) : "f"(s))
#define UNPK2(lo, hi, s) asm("mov.b64 {%0, %1}, %2;" : "=f"(lo), "=f"(hi) : "l"(s))

// fast activations (MUFU-based; |err| ~1e-6, budget 1e-3)
__device__ __forceinline__ float fsig(float x)  { return 1.f / (1.f + __expf(-x)); }
__device__ __forceinline__ float ftanh(float x) { return 1.f - 2.f / (__expf(2.f * x) + 1.f); }

// ---------------- scratch (static device globals; no runtime alloc) ----------
__device__ float g_xg2[2u * 4 * (SEQ * BATCH) * HDIM];   // [d][gate][m][j]
__device__ float g_hseq[2u * SEQ * BATCH * HDIM];        // f32 h for feats
// h as pre-packed mma B-fragment words: slot = (d*SEQ+t)*2+bh, 4096 words/slot.
// word = slot*4096 + ktile*128 + (nt*2+reg)*32 + lane.  Slot 1024 = zeros (step 0).
__device__ uint32_t g_hfrag_hi[1025u * 4096u];
__device__ uint32_t g_hfrag_lo[1025u * 4096u];
__device__ float g_feats[SEQ * BATCH * TTAGS];
__device__ int   g_cnt[4 * 32];                          // group counters at [g*32]

// m16n8k16 bf16 HMMA (sm_80+ baseline PTX; compiles for compute_103)
__device__ __forceinline__ void mma16816(float* c, const uint32_t* a, const uint32_t* b) {
    asm volatile(
        "mma.sync.aligned.m16n8k16.row.col.f32.bf16.bf16.f32 "
        "{%0,%1,%2,%3}, {%4,%5,%6,%7}, {%8,%9}, {%0,%1,%2,%3};"
        : "+f"(c[0]), "+f"(c[1]), "+f"(c[2]), "+f"(c[3])
        : "r"(a[0]), "r"(a[1]), "r"(a[2]), "r"(a[3]), "r"(b[0]), "r"(b[1]));
}

// ---------------------------------------------------------------------------
__global__ void dummy_kernel() {}   // keeps ncu -s 5 window on recur_kernel

// ---------------------------------------------------------------------------
// Kernel 1: xg2[d][gate][m][j]  (unchanged; also resets barrier counters)
// ---------------------------------------------------------------------------
__global__ void __launch_bounds__(256) xg_kernel(
    const int* __restrict__ tokens, const float* __restrict__ emb,
    const float* __restrict__ wf, const float* __restrict__ bf,
    const float* __restrict__ wb, const float* __restrict__ bb)
{
    const int bm = blockIdx.x;          // 64
    const int bn = blockIdx.y;          // 16
    const int dir = blockIdx.z;         // 2
    const int tid = threadIdx.x;

    if (bm == 0 && bn == 0 && dir == 0 && tid < 4) g_cnt[tid * 32] = 0;

    const float* w    = dir ? wb : wf;
    const float* bias = dir ? bb : bf;

    __shared__ int   rowtok[128];
    __shared__ __align__(16) float As[16 * 132];
    __shared__ __align__(16) float Bs[16 * 132];

    if (tid < 128) {
        int mg = bm * 128 + tid;
        rowtok[tid] = tokens[(mg & 31) * SEQ + (mg >> 5)];
    }
    __syncthreads();

    const int ty = tid >> 4;
    const int tx = tid & 15;

    uint64_t acc[4][8];
    #pragma unroll
    for (int i = 0; i < 4; i++)
        #pragma unroll
        for (int j = 0; j < 8; j++) acc[i][j] = 0ull;

    for (int k0 = 0; k0 < EDIM; k0 += 16) {
        #pragma unroll
        for (int it = 0; it < 2; ++it) {
            int f4 = tid + it * 256;
            int m = f4 >> 2, kq = f4 & 3;
            float4 v = *(const float4*)(emb + (size_t)rowtok[m] * EDIM + k0 + kq * 4);
            As[(kq * 4 + 0) * 132 + m] = v.x;
            As[(kq * 4 + 1) * 132 + m] = v.y;
            As[(kq * 4 + 2) * 132 + m] = v.z;
            As[(kq * 4 + 3) * 132 + m] = v.w;
        }
        #pragma unroll
        for (int it = 0; it < 2; ++it) {
            int f4 = tid + it * 256;
            int n = f4 >> 2, kq = f4 & 3;
            float4 v = *(const float4*)(w + (size_t)(bn * 128 + n) * EDIM + k0 + kq * 4);
            Bs[(kq * 4 + 0) * 132 + n] = v.x;
            Bs[(kq * 4 + 1) * 132 + n] = v.y;
            Bs[(kq * 4 + 2) * 132 + n] = v.z;
            Bs[(kq * 4 + 3) * 132 + n] = v.w;
        }
        __syncthreads();
        #pragma unroll
        for (int k = 0; k < 16; k++) {
            ulonglong2 a0 = *(const ulonglong2*)(As + k * 132 + ty * 8);
            ulonglong2 a1 = *(const ulonglong2*)(As + k * 132 + ty * 8 + 4);
            float4 b0 = *(const float4*)(Bs + k * 132 + tx * 8);
            float4 b1 = *(const float4*)(Bs + k * 132 + tx * 8 + 4);
            float bv[8] = {b0.x, b0.y, b0.z, b0.w, b1.x, b1.y, b1.z, b1.w};
            uint64_t a2[4] = {a0.x, a0.y, a1.x, a1.y};
            #pragma unroll
            for (int j = 0; j < 8; j++) {
                uint64_t bs; SPLAT2(bs, bv[j]);
                FMA2(acc[0][j], a2[0], bs);
                FMA2(acc[1][j], a2[1], bs);
                FMA2(acc[2][j], a2[2], bs);
                FMA2(acc[3][j], a2[3], bs);
            }
        }
        __syncthreads();
    }

    float bb8[8];
    #pragma unroll
    for (int j = 0; j < 8; j++) bb8[j] = bias[bn * 128 + tx * 8 + j];

    const int gate = bn >> 2;
    const int jb   = (bn & 3) * 128 + tx * 8;

    #pragma unroll
    for (int mp = 0; mp < 4; mp++) {
        float r0[8], r1[8];
        #pragma unroll
        for (int j = 0; j < 8; j++) {
            float lo, hi; UNPK2(lo, hi, acc[mp][j]);
            r0[j] = lo + bb8[j];
            r1[j] = hi + bb8[j];
        }
        int m0 = bm * 128 + ty * 8 + mp * 2;
        float* o0 = g_xg2 + (((size_t)dir * 4 + gate) * 8192 + m0) * HDIM + jb;
        float* o1 = o0 + HDIM;
        *(float4*)(o0)     = make_float4(r0[0], r0[1], r0[2], r0[3]);
        *(float4*)(o0 + 4) = make_float4(r0[4], r0[5], r0[6], r0[7]);
        *(float4*)(o1)     = make_float4(r1[0], r1[1], r1[2], r1[3]);
        *(float4*)(o1 + 4) = make_float4(r1[4], r1[5], r1[6], r1[7]);
    }
}

// ---------------------------------------------------------------------------
// Kernel 2: persistent BiLSTM recurrence on HMMA (mma.sync bf16, split hi/lo).
// 128 blocks = (dir, 32 chunks of 16 units -> 64 gate rows, 2 batch halves).
// Warp w owns k-slice [64w,64w+64): W fragments resident in registers.
// h moves as pre-packed B-fragment words through global (coalesced LDG.32).
// ---------------------------------------------------------------------------
__global__ void __launch_bounds__(256, 1) recur_kernel(
    const float* __restrict__ whhf, const float* __restrict__ whhb)
{
    __shared__ float part[8 * 64 * 17];   // [w][row 0..63][b 0..15] padded

    const int tid = threadIdx.x;
    const int w   = tid >> 5;
    const int lid = tid & 31;
    const int g   = lid >> 2;             // mma groupID
    const int tq  = lid & 3;              // mma threadID_in_group

    const int bid   = blockIdx.x;
    const int dir   = bid >> 6;
    const int sub   = bid & 63;
    const int chunk = sub >> 1;            // 0..31, 16 units each
    const int bh    = sub & 1;
    const int j0    = chunk * 16;

    // cell role: one (u, bt) per thread
    const int u  = tid & 15;
    const int bt = tid >> 4;

    int* cnt = g_cnt + (dir * 2 + bh) * 32;

    // ---- one-time: W fragments (hi/lo split) into registers ----
    const float* whh = dir ? whhb : whhf;
    uint32_t ahi[4][4][4], alo[4][4][4];   // [mt=gate][kt][reg]
    #pragma unroll
    for (int mt = 0; mt < 4; mt++)
        #pragma unroll
        for (int kt = 0; kt < 4; kt++)
            #pragma unroll
            for (int reg = 0; reg < 4; reg++) {
                int urow = g + (reg & 1) * 8;              // within 16-unit tile
                int grow = mt * HDIM + j0 + urow;          // row in W[2048]
                int k    = w * 64 + kt * 16 + 2 * tq + (reg >> 1) * 8;
                float v0 = whh[(size_t)grow * HDIM + k];
                float v1 = whh[(size_t)grow * HDIM + k + 1];
                __nv_bfloat16 h0 = __float2bfloat16(v0);
                __nv_bfloat16 h1 = __float2bfloat16(v1);
                __nv_bfloat16 l0 = __float2bfloat16(v0 - __bfloat162float(h0));
                __nv_bfloat16 l1 = __float2bfloat16(v1 - __bfloat162float(h1));
                ahi[mt][kt][reg] = (uint32_t)__bfloat16_as_ushort(h0)
                                 | ((uint32_t)__bfloat16_as_ushort(h1) << 16);
                alo[mt][kt][reg] = (uint32_t)__bfloat16_as_ushort(l0)
                                 | ((uint32_t)__bfloat16_as_ushort(l1) << 16);
            }

    float c = 0.f;                         // cell state (dir, j0+u, bh*16+bt)

    for (int step = 0; step < SEQ; ++step) {
        const int t = dir ? (SEQ - 1 - step) : step;

        // ---- group barrier (REDG + same-address acquire poll) ----
        __syncthreads();                   // h-frag stores of prev step issued
        if (tid == 0) {
            asm volatile("red.release.gpu.global.add.s32 [%0], %1;" :: "l"(cnt), "r"(1) : "memory");
            const int target = 32 * (step + 1);
            int v;
            do {
                asm volatile("ld.acquire.gpu.global.s32 %0, [%1];" : "=r"(v) : "l"(cnt) : "memory");
            } while (v < target);
        }

        // xg prefetch (independent of h; overlaps tid0 poll)
        float xgv[4];
        #pragma unroll
        for (int gate = 0; gate < 4; gate++)
            xgv[gate] = __ldg(g_xg2 +
                ((size_t)(dir * 4 + gate) * 8192 + (size_t)t * 32 + bh * 16 + bt) * HDIM + j0 + u);

        __syncthreads();                   // publishes acquire to whole block

        // ---- load B fragments (coalesced; slot written by producers) ----
        const uint32_t slot = (step == 0) ? 1024u
            : (uint32_t)((dir * SEQ + (dir ? t + 1 : t - 1)) * 2 + bh);
        const uint32_t* bhp = g_hfrag_hi + (size_t)slot * 4096u + (uint32_t)(w * 4) * 128u;
        const uint32_t* blp = g_hfrag_lo + (size_t)slot * 4096u + (uint32_t)(w * 4) * 128u;
        uint32_t bhi[4][2][2], blo[4][2][2];
        #pragma unroll
        for (int kt = 0; kt < 4; kt++)
            #pragma unroll
            for (int nt = 0; nt < 2; nt++)
                #pragma unroll
                for (int reg = 0; reg < 2; reg++) {
                    int idx = kt * 128 + (nt * 2 + reg) * 32 + lid;
                    bhi[kt][nt][reg] = bhp[idx];
                    blo[kt][nt][reg] = blp[idx];
                }

        // ---- MMAs: (Whi+Wlo)(hhi+hlo) minus lo*lo ----
        float acc[4][2][4];
        #pragma unroll
        for (int mt = 0; mt < 4; mt++)
            #pragma unroll
            for (int nt = 0; nt < 2; nt++)
                #pragma unroll
                for (int q = 0; q < 4; q++) acc[mt][nt][q] = 0.f;
        #pragma unroll
        for (int kt = 0; kt < 4; kt++)
            #pragma unroll
            for (int mt = 0; mt < 4; mt++)
                #pragma unroll
                for (int nt = 0; nt < 2; nt++) {
                    mma16816(acc[mt][nt], ahi[mt][kt], bhi[kt][nt]);
                    mma16816(acc[mt][nt], ahi[mt][kt], blo[kt][nt]);
                    mma16816(acc[mt][nt], alo[mt][kt], bhi[kt][nt]);
                }

        // ---- write partials to smem ----
        #pragma unroll
        for (int mt = 0; mt < 4; mt++)
            #pragma unroll
            for (int nt = 0; nt < 2; nt++) {
                int row0 = mt * 16 + g;
                int col0 = nt * 8 + 2 * tq;
                part[(w * 64 + row0) * 17 + col0]         = acc[mt][nt][0];
                part[(w * 64 + row0) * 17 + col0 + 1]     = acc[mt][nt][1];
                part[(w * 64 + row0 + 8) * 17 + col0]     = acc[mt][nt][2];
                part[(w * 64 + row0 + 8) * 17 + col0 + 1] = acc[mt][nt][3];
            }
        __syncthreads();

        // ---- reduce across 8 k-slices + LSTM cell for (u, bt) ----
        float gi = xgv[0], gf = xgv[1], gg = xgv[2], go = xgv[3];
        #pragma unroll
        for (int kw = 0; kw < 8; kw++) {
            gi += part[(kw * 64 +  0 + u) * 17 + bt];
            gf += part[(kw * 64 + 16 + u) * 17 + bt];
            gg += part[(kw * 64 + 32 + u) * 17 + bt];
            go += part[(kw * 64 + 48 + u) * 17 + bt];
        }
        c = fsig(gf) * c + fsig(gi) * ftanh(gg);
        float h = fsig(go) * ftanh(c);

        g_hseq[((size_t)(dir * SEQ + t) * BATCH + bh * 16 + bt) * HDIM + j0 + u] = h;

        // ---- pack h into B-fragment words (pairs along u via shfl) ----
        float ho = __shfl_xor_sync(0xffffffffu, h, 1);   // partner u^1, same bt
        if ((u & 1) == 0) {
            __nv_bfloat16 hh0 = __float2bfloat16(h);
            __nv_bfloat16 hh1 = __float2bfloat16(ho);
            __nv_bfloat16 hl0 = __float2bfloat16(h  - __bfloat162float(hh0));
            __nv_bfloat16 hl1 = __float2bfloat16(ho - __bfloat162float(hh1));
            uint32_t whi = (uint32_t)__bfloat16_as_ushort(hh0)
                         | ((uint32_t)__bfloat16_as_ushort(hh1) << 16);
            uint32_t wlo = (uint32_t)__bfloat16_as_ushort(hl0)
                         | ((uint32_t)__bfloat16_as_ushort(hl1) << 16);
            int reg = u >> 3;
            int tq2 = (u & 7) >> 1;
            int nt2 = bt >> 3;
            int g2  = bt & 7;
            uint32_t slotW = (uint32_t)((dir * SEQ + t) * 2 + bh);
            size_t idx = (size_t)slotW * 4096u + (uint32_t)chunk * 128u
                       + (uint32_t)((nt2 * 2 + reg) * 32 + g2 * 4 + tq2);
            g_hfrag_hi[idx] = whi;
            g_hfrag_lo[idx] = wlo;
        }
    }
}

// ---------------------------------------------------------------------------
// Kernel 3: feats (unchanged)
// ---------------------------------------------------------------------------
__global__ void __launch_bounds__(256) feats_kernel(
    const float* __restrict__ w_out, const float* __restrict__ b_out)
{
    const int s = blockIdx.x;
    const int w = threadIdx.x >> 5;
    const int l = threadIdx.x & 31;

    for (int b = w; b < BATCH; b += 8) {
        const float* hf = g_hseq + ((size_t)(0 * SEQ + s) * BATCH + b) * HDIM;
        const float* hb = g_hseq + ((size_t)(1 * SEQ + s) * BATCH + b) * HDIM;
        float hv[32];
        #pragma unroll
        for (int i = 0; i < 16; i++) hv[i]      = hf[l + 32 * i];
        #pragma unroll
        for (int i = 0; i < 16; i++) hv[16 + i] = hb[l + 32 * i];
        for (int tag = 0; tag < TTAGS; tag++) {
            const float* wr = w_out + (size_t)tag * (2 * HDIM);
            float p = 0.f;
            #pragma unroll
            for (int i = 0; i < 16; i++) p = fmaf(hv[i],      wr[l + 32 * i],        p);
            #pragma unroll
            for (int i = 0; i < 16; i++) p = fmaf(hv[16 + i], wr[HDIM + l + 32 * i], p);
            #pragma unroll
            for (int o = 16; o; o >>= 1) p += __shfl_down_sync(0xffffffffu, p, o);
            if (l == 0) g_feats[(s * BATCH + b) * TTAGS + tag] = p + b_out[tag];
        }
    }
}

// ---------------------------------------------------------------------------
// Kernel 4: CRF forward (unchanged)
// ---------------------------------------------------------------------------
__global__ void __launch_bounds__(32) crf_kernel(
    const int* __restrict__ lengths, const float* __restrict__ trans,
    float* __restrict__ out)
{
    const int b = blockIdx.x;
    const int l = threadIdx.x;

    __shared__ float fb[SEQ * TTAGS];
    __shared__ float es[32];
    for (int i = l; i < SEQ * TTAGS; i += 32) {
        int s = i / TTAGS, tg = i - s * TTAGS;
        fb[i] = g_feats[(s * BATCH + b) * TTAGS + tg];
    }

    float et[TTAGS];
    if (l < TTAGS) {
        #pragma unroll
        for (int p = 0; p < TTAGS; p++) et[p] = expf(trans[l * TTAGS + p]);
    }
    float fv = (l == START_TAG) ? 0.f : NEGV;
    es[l] = 0.f;
    __syncwarp();

    const int len = lengths[b];
    for (int s = 0; s < len; s++) {
        float v = (l < TTAGS) ? fv : -1e30f;
        #pragma unroll
        for (int o = 8; o; o >>= 1) v = fmaxf(v, __shfl_xor_sync(0xffffffffu, v, o));
        float e = (l < TTAGS) ? expf(fv - v) : 0.f;
        es[l] = e;
        __syncwarp();
        float sa = 0.f, sb = 0.f;
        #pragma unroll
        for (int p = 0; p < TTAGS; p += 2) {
            sa = fmaf(es[p],     et[p],     sa);
            sb = fmaf(es[p + 1], et[p + 1], sb);
        }
        if (l < TTAGS) fv = v + logf(sa + sb) + fb[s * TTAGS + l];
        __syncwarp();
    }

    float term = (l < TTAGS) ? (fv + trans[STOP_TAG * TTAGS + l]) : -1e30f;
    float mx = term;
    #pragma unroll
    for (int o = 16; o; o >>= 1) mx = fmaxf(mx, __shfl_xor_sync(0xffffffffu, mx, o));
    float e = (l < TTAGS) ? expf(term - mx) : 0.f;
    #pragma unroll
    for (int o = 16; o; o >>= 1) e += __shfl_xor_sync(0xffffffffu, e, o);
    if (l == 0) out[b] = (mx + logf(e)) / (float)len;
}

// ---------------------------------------------------------------------------
extern "C" void kernel_launch(void* const* d_in, const int* in_sizes, int n_in,
                              void* d_out, int out_size)
{
    const int*   tokens  = (const int*)  d_in[0];
    const int*   lengths = (const int*)  d_in[1];
    const float* emb     = (const float*)d_in[2];
    const float* w_ih_f  = (const float*)d_in[3];
    const float* w_hh_f  = (const float*)d_in[4];
    const float* b_f     = (const float*)d_in[5];
    const float* w_ih_b  = (const float*)d_in[6];
    const float* w_hh_b  = (const float*)d_in[7];
    const float* b_b     = (const float*)d_in[8];
    const float* w_out   = (const float*)d_in[9];
    const float* b_out   = (const float*)d_in[10];
    const float* trans   = (const float*)d_in[11];
    float* out = (float*)d_out;

    dummy_kernel<<<1, 32>>>();
    dummy_kernel<<<1, 32>>>();
    xg_kernel<<<dim3(64, 16, 2), 256>>>(tokens, emb, w_ih_f, b_f, w_ih_b, b_b);
    recur_kernel<<<128, 256>>>(w_hh_f, w_hh_b);
    feats_kernel<<<SEQ, 256>>>(w_out, b_out);
    crf_kernel<<<BATCH, 32>>>(lengths, trans, out);
}

// round 13
// speedup vs baseline: 2.7311x; 1.0624x over previous
#include <cuda_runtime.h>
#include <cuda_bf16.h>
#include <math.h>
#include <stdint.h>

// Problem dims (fixed)
#define SEQ 256
#define BATCH 32
#define EDIM 256
#define HDIM 512
#define GDIM 2048           // 4*H
#define TTAGS 10
#define START_TAG 8
#define STOP_TAG 9
#define NEGV -10000.0f

// packed fp32x2 helpers (xg kernel)
#define FMA2(acc, a, b) asm("fma.rn.f32x2 %0, %1, %2, %3;" : "=l"(acc) : "l"(a), "l"(b), "l"(acc))
#define SPLAT2(d, s)    asm("mov.b64 %0, {%1, %1};" : "=l"(d) : "f"(s))
#define UNPK2(lo, hi, s) asm("mov.b64 {%0, %1}, %2;" : "=f"(lo), "=f"(hi) : "l"(s))

// fast activations (MUFU-based; |err| ~1e-6, budget 1e-3)
__device__ __forceinline__ float fsig(float x)  { return 1.f / (1.f + __expf(-x)); }
__device__ __forceinline__ float ftanh(float x) { return 1.f - 2.f / (__expf(2.f * x) + 1.f); }

// ---------------- scratch (static device globals; no runtime alloc) ----------
__device__ float g_xg2[2u * 4 * (SEQ * BATCH) * HDIM];   // [d][gate][m][j]
__device__ float g_hseq[2u * SEQ * BATCH * HDIM];        // f32 h for feats
// h as pre-packed mma B-fragment words: slot = (d*SEQ+t)*2+bh, 4096 words/slot.
// word idx = slot*4096 + ktile*128 + lane*4 + q, q = nt*2+reg  (LDG.128-friendly).
// Slot 1024 = zeros (step 0).
__device__ uint32_t g_hfrag_hi[1025u * 4096u];
__device__ uint32_t g_hfrag_lo[1025u * 4096u];
__device__ float g_feats[SEQ * BATCH * TTAGS];
__device__ int   g_cnt[4 * 32];                          // group counters at [g*32]

// m16n8k16 bf16 HMMA (sm_80+ baseline PTX; compiles for compute_103)
__device__ __forceinline__ void mma16816(float* c, const uint32_t* a, const uint32_t* b) {
    asm volatile(
        "mma.sync.aligned.m16n8k16.row.col.f32.bf16.bf16.f32 "
        "{%0,%1,%2,%3}, {%4,%5,%6,%7}, {%8,%9}, {%0,%1,%2,%3};"
        : "+f"(c[0]), "+f"(c[1]), "+f"(c[2]), "+f"(c[3])
        : "r"(a[0]), "r"(a[1]), "r"(a[2]), "r"(a[3]), "r"(b[0]), "r"(b[1]));
}

// ---------------------------------------------------------------------------
__global__ void dummy_kernel() {}   // keeps ncu -s 5 window on recur_kernel

// ---------------------------------------------------------------------------
// Kernel 1: xg2[d][gate][m][j]  (unchanged; also resets barrier counters)
// ---------------------------------------------------------------------------
__global__ void __launch_bounds__(256) xg_kernel(
    const int* __restrict__ tokens, const float* __restrict__ emb,
    const float* __restrict__ wf, const float* __restrict__ bf,
    const float* __restrict__ wb, const float* __restrict__ bb)
{
    const int bm = blockIdx.x;          // 64
    const int bn = blockIdx.y;          // 16
    const int dir = blockIdx.z;         // 2
    const int tid = threadIdx.x;

    if (bm == 0 && bn == 0 && dir == 0 && tid < 4) g_cnt[tid * 32] = 0;

    const float* w    = dir ? wb : wf;
    const float* bias = dir ? bb : bf;

    __shared__ int   rowtok[128];
    __shared__ __align__(16) float As[16 * 132];
    __shared__ __align__(16) float Bs[16 * 132];

    if (tid < 128) {
        int mg = bm * 128 + tid;
        rowtok[tid] = tokens[(mg & 31) * SEQ + (mg >> 5)];
    }
    __syncthreads();

    const int ty = tid >> 4;
    const int tx = tid & 15;

    uint64_t acc[4][8];
    #pragma unroll
    for (int i = 0; i < 4; i++)
        #pragma unroll
        for (int j = 0; j < 8; j++) acc[i][j] = 0ull;

    for (int k0 = 0; k0 < EDIM; k0 += 16) {
        #pragma unroll
        for (int it = 0; it < 2; ++it) {
            int f4 = tid + it * 256;
            int m = f4 >> 2, kq = f4 & 3;
            float4 v = *(const float4*)(emb + (size_t)rowtok[m] * EDIM + k0 + kq * 4);
            As[(kq * 4 + 0) * 132 + m] = v.x;
            As[(kq * 4 + 1) * 132 + m] = v.y;
            As[(kq * 4 + 2) * 132 + m] = v.z;
            As[(kq * 4 + 3) * 132 + m] = v.w;
        }
        #pragma unroll
        for (int it = 0; it < 2; ++it) {
            int f4 = tid + it * 256;
            int n = f4 >> 2, kq = f4 & 3;
            float4 v = *(const float4*)(w + (size_t)(bn * 128 + n) * EDIM + k0 + kq * 4);
            Bs[(kq * 4 + 0) * 132 + n] = v.x;
            Bs[(kq * 4 + 1) * 132 + n] = v.y;
            Bs[(kq * 4 + 2) * 132 + n] = v.z;
            Bs[(kq * 4 + 3) * 132 + n] = v.w;
        }
        __syncthreads();
        #pragma unroll
        for (int k = 0; k < 16; k++) {
            ulonglong2 a0 = *(const ulonglong2*)(As + k * 132 + ty * 8);
            ulonglong2 a1 = *(const ulonglong2*)(As + k * 132 + ty * 8 + 4);
            float4 b0 = *(const float4*)(Bs + k * 132 + tx * 8);
            float4 b1 = *(const float4*)(Bs + k * 132 + tx * 8 + 4);
            float bv[8] = {b0.x, b0.y, b0.z, b0.w, b1.x, b1.y, b1.z, b1.w};
            uint64_t a2[4] = {a0.x, a0.y, a1.x, a1.y};
            #pragma unroll
            for (int j = 0; j < 8; j++) {
                uint64_t bs; SPLAT2(bs, bv[j]);
                FMA2(acc[0][j], a2[0], bs);
                FMA2(acc[1][j], a2[1], bs);
                FMA2(acc[2][j], a2[2], bs);
                FMA2(acc[3][j], a2[3], bs);
            }
        }
        __syncthreads();
    }

    float bb8[8];
    #pragma unroll
    for (int j = 0; j < 8; j++) bb8[j] = bias[bn * 128 + tx * 8 + j];

    const int gate = bn >> 2;
    const int jb   = (bn & 3) * 128 + tx * 8;

    #pragma unroll
    for (int mp = 0; mp < 4; mp++) {
        float r0[8], r1[8];
        #pragma unroll
        for (int j = 0; j < 8; j++) {
            float lo, hi; UNPK2(lo, hi, acc[mp][j]);
            r0[j] = lo + bb8[j];
            r1[j] = hi + bb8[j];
        }
        int m0 = bm * 128 + ty * 8 + mp * 2;
        float* o0 = g_xg2 + (((size_t)dir * 4 + gate) * 8192 + m0) * HDIM + jb;
        float* o1 = o0 + HDIM;
        *(float4*)(o0)     = make_float4(r0[0], r0[1], r0[2], r0[3]);
        *(float4*)(o0 + 4) = make_float4(r0[4], r0[5], r0[6], r0[7]);
        *(float4*)(o1)     = make_float4(r1[0], r1[1], r1[2], r1[3]);
        *(float4*)(o1 + 4) = make_float4(r1[4], r1[5], r1[6], r1[7]);
    }
}

// ---------------------------------------------------------------------------
// Kernel 2: persistent BiLSTM recurrence on HMMA (mma.sync bf16, split hi/lo).
// 128 blocks = (dir, 32 chunks of 16 units -> 64 gate rows, 2 batch halves).
// Warp w owns k-slice [64w,64w+64): W fragments resident in registers.
// h fragments via LDG.128 (4 hi + 4 lo per thread); all-lanes acquire poll.
// ---------------------------------------------------------------------------
__global__ void __launch_bounds__(256, 1) recur_kernel(
    const float* __restrict__ whhf, const float* __restrict__ whhb)
{
    __shared__ float part[8 * 64 * 17];   // [w][row 0..63][b 0..15] padded

    const int tid = threadIdx.x;
    const int w   = tid >> 5;
    const int lid = tid & 31;
    const int g   = lid >> 2;             // mma groupID
    const int tq  = lid & 3;              // mma threadID_in_group

    const int bid   = blockIdx.x;
    const int dir   = bid >> 6;
    const int sub   = bid & 63;
    const int chunk = sub >> 1;            // 0..31, 16 units each
    const int bh    = sub & 1;
    const int j0    = chunk * 16;

    // cell role: one (u, bt) per thread
    const int u  = tid & 15;
    const int bt = tid >> 4;

    int* cnt = g_cnt + (dir * 2 + bh) * 32;

    // ---- one-time: W fragments (hi/lo split) into registers ----
    const float* whh = dir ? whhb : whhf;
    uint32_t ahi[4][4][4], alo[4][4][4];   // [mt=gate][kt][reg]
    #pragma unroll
    for (int mt = 0; mt < 4; mt++)
        #pragma unroll
        for (int kt = 0; kt < 4; kt++)
            #pragma unroll
            for (int reg = 0; reg < 4; reg++) {
                int urow = g + (reg & 1) * 8;              // within 16-unit tile
                int grow = mt * HDIM + j0 + urow;          // row in W[2048]
                int k    = w * 64 + kt * 16 + 2 * tq + (reg >> 1) * 8;
                float v0 = whh[(size_t)grow * HDIM + k];
                float v1 = whh[(size_t)grow * HDIM + k + 1];
                __nv_bfloat16 h0 = __float2bfloat16(v0);
                __nv_bfloat16 h1 = __float2bfloat16(v1);
                __nv_bfloat16 l0 = __float2bfloat16(v0 - __bfloat162float(h0));
                __nv_bfloat16 l1 = __float2bfloat16(v1 - __bfloat162float(h1));
                ahi[mt][kt][reg] = (uint32_t)__bfloat16_as_ushort(h0)
                                 | ((uint32_t)__bfloat16_as_ushort(h1) << 16);
                alo[mt][kt][reg] = (uint32_t)__bfloat16_as_ushort(l0)
                                 | ((uint32_t)__bfloat16_as_ushort(l1) << 16);
            }

    float c = 0.f;                         // cell state (dir, j0+u, bh*16+bt)

    for (int step = 0; step < SEQ; ++step) {
        const int t = dir ? (SEQ - 1 - step) : step;

        // ---- group barrier: REDG arrive; ALL lanes acquire-poll (same addr) ----
        __syncthreads();                   // h-frag stores of prev step done CTA-wide
        if (tid == 0)
            asm volatile("red.release.gpu.global.add.s32 [%0], %1;" :: "l"(cnt), "r"(1) : "memory");

        // xg prefetch (independent of h; issues before the poll loop)
        float xgv[4];
        #pragma unroll
        for (int gate = 0; gate < 4; gate++)
            xgv[gate] = __ldg(g_xg2 +
                ((size_t)(dir * 4 + gate) * 8192 + (size_t)t * 32 + bh * 16 + bt) * HDIM + j0 + u);

        {
            const int target = 32 * (step + 1);
            int v;
            do {
                asm volatile("ld.acquire.gpu.global.s32 %0, [%1];" : "=r"(v) : "l"(cnt) : "memory");
            } while (v < target);
        }

        // ---- load B fragments: 4 hi + 4 lo LDG.128 per thread ----
        const uint32_t slot = (step == 0) ? 1024u
            : (uint32_t)((dir * SEQ + (dir ? t + 1 : t - 1)) * 2 + bh);
        const uint4* bhp = (const uint4*)(g_hfrag_hi + (size_t)slot * 4096u) + (w * 4) * 32 + lid;
        const uint4* blp = (const uint4*)(g_hfrag_lo + (size_t)slot * 4096u) + (w * 4) * 32 + lid;
        uint32_t bhi[4][2][2], blo[4][2][2];
        #pragma unroll
        for (int kt = 0; kt < 4; kt++) {
            uint4 vh = bhp[kt * 32];
            uint4 vl = blp[kt * 32];
            bhi[kt][0][0] = vh.x; bhi[kt][0][1] = vh.y;
            bhi[kt][1][0] = vh.z; bhi[kt][1][1] = vh.w;
            blo[kt][0][0] = vl.x; blo[kt][0][1] = vl.y;
            blo[kt][1][0] = vl.z; blo[kt][1][1] = vl.w;
        }

        // ---- MMAs: (Whi+Wlo)(hhi+hlo) minus lo*lo ----
        float acc[4][2][4];
        #pragma unroll
        for (int mt = 0; mt < 4; mt++)
            #pragma unroll
            for (int nt = 0; nt < 2; nt++)
                #pragma unroll
                for (int q = 0; q < 4; q++) acc[mt][nt][q] = 0.f;
        #pragma unroll
        for (int kt = 0; kt < 4; kt++)
            #pragma unroll
            for (int mt = 0; mt < 4; mt++)
                #pragma unroll
                for (int nt = 0; nt < 2; nt++) {
                    mma16816(acc[mt][nt], ahi[mt][kt], bhi[kt][nt]);
                    mma16816(acc[mt][nt], ahi[mt][kt], blo[kt][nt]);
                    mma16816(acc[mt][nt], alo[mt][kt], bhi[kt][nt]);
                }

        // ---- write partials to smem ----
        #pragma unroll
        for (int mt = 0; mt < 4; mt++)
            #pragma unroll
            for (int nt = 0; nt < 2; nt++) {
                int row0 = mt * 16 + g;
                int col0 = nt * 8 + 2 * tq;
                part[(w * 64 + row0) * 17 + col0]         = acc[mt][nt][0];
                part[(w * 64 + row0) * 17 + col0 + 1]     = acc[mt][nt][1];
                part[(w * 64 + row0 + 8) * 17 + col0]     = acc[mt][nt][2];
                part[(w * 64 + row0 + 8) * 17 + col0 + 1] = acc[mt][nt][3];
            }
        __syncthreads();

        // ---- reduce across 8 k-slices + LSTM cell for (u, bt) ----
        float gi = xgv[0], gf = xgv[1], gg = xgv[2], go = xgv[3];
        #pragma unroll
        for (int kw = 0; kw < 8; kw++) {
            gi += part[(kw * 64 +  0 + u) * 17 + bt];
            gf += part[(kw * 64 + 16 + u) * 17 + bt];
            gg += part[(kw * 64 + 32 + u) * 17 + bt];
            go += part[(kw * 64 + 48 + u) * 17 + bt];
        }
        c = fsig(gf) * c + fsig(gi) * ftanh(gg);
        float h = fsig(go) * ftanh(c);

        g_hseq[((size_t)(dir * SEQ + t) * BATCH + bh * 16 + bt) * HDIM + j0 + u] = h;

        // ---- pack h into B-fragment words (pairs along u via shfl) ----
        float ho = __shfl_xor_sync(0xffffffffu, h, 1);   // partner u^1, same bt
        if ((u & 1) == 0) {
            __nv_bfloat16 hh0 = __float2bfloat16(h);
            __nv_bfloat16 hh1 = __float2bfloat16(ho);
            __nv_bfloat16 hl0 = __float2bfloat16(h  - __bfloat162float(hh0));
            __nv_bfloat16 hl1 = __float2bfloat16(ho - __bfloat162float(hh1));
            uint32_t whi = (uint32_t)__bfloat16_as_ushort(hh0)
                         | ((uint32_t)__bfloat16_as_ushort(hh1) << 16);
            uint32_t wlo = (uint32_t)__bfloat16_as_ushort(hl0)
                         | ((uint32_t)__bfloat16_as_ushort(hl1) << 16);
            int reg = u >> 3;
            int tq2 = (u & 7) >> 1;
            int nt2 = bt >> 3;
            int g2  = bt & 7;
            uint32_t slotW = (uint32_t)((dir * SEQ + t) * 2 + bh);
            size_t idx = (size_t)slotW * 4096u + (uint32_t)chunk * 128u
                       + (uint32_t)((g2 * 4 + tq2) * 4 + nt2 * 2 + reg);
            g_hfrag_hi[idx] = whi;
            g_hfrag_lo[idx] = wlo;
        }
    }
}

// ---------------------------------------------------------------------------
// Kernel 3: feats (unchanged)
// ---------------------------------------------------------------------------
__global__ void __launch_bounds__(256) feats_kernel(
    const float* __restrict__ w_out, const float* __restrict__ b_out)
{
    const int s = blockIdx.x;
    const int w = threadIdx.x >> 5;
    const int l = threadIdx.x & 31;

    for (int b = w; b < BATCH; b += 8) {
        const float* hf = g_hseq + ((size_t)(0 * SEQ + s) * BATCH + b) * HDIM;
        const float* hb = g_hseq + ((size_t)(1 * SEQ + s) * BATCH + b) * HDIM;
        float hv[32];
        #pragma unroll
        for (int i = 0; i < 16; i++) hv[i]      = hf[l + 32 * i];
        #pragma unroll
        for (int i = 0; i < 16; i++) hv[16 + i] = hb[l + 32 * i];
        for (int tag = 0; tag < TTAGS; tag++) {
            const float* wr = w_out + (size_t)tag * (2 * HDIM);
            float p = 0.f;
            #pragma unroll
            for (int i = 0; i < 16; i++) p = fmaf(hv[i],      wr[l + 32 * i],        p);
            #pragma unroll
            for (int i = 0; i < 16; i++) p = fmaf(hv[16 + i], wr[HDIM + l + 32 * i], p);
            #pragma unroll
            for (int o = 16; o; o >>= 1) p += __shfl_down_sync(0xffffffffu, p, o);
            if (l == 0) g_feats[(s * BATCH + b) * TTAGS + tag] = p + b_out[tag];
        }
    }
}

// ---------------------------------------------------------------------------
// Kernel 4: CRF forward (unchanged)
// ---------------------------------------------------------------------------
__global__ void __launch_bounds__(32) crf_kernel(
    const int* __restrict__ lengths, const float* __restrict__ trans,
    float* __restrict__ out)
{
    const int b = blockIdx.x;
    const int l = threadIdx.x;

    __shared__ float fb[SEQ * TTAGS];
    __shared__ float es[32];
    for (int i = l; i < SEQ * TTAGS; i += 32) {
        int s = i / TTAGS, tg = i - s * TTAGS;
        fb[i] = g_feats[(s * BATCH + b) * TTAGS + tg];
    }

    float et[TTAGS];
    if (l < TTAGS) {
        #pragma unroll
        for (int p = 0; p < TTAGS; p++) et[p] = expf(trans[l * TTAGS + p]);
    }
    float fv = (l == START_TAG) ? 0.f : NEGV;
    es[l] = 0.f;
    __syncwarp();

    const int len = lengths[b];
    for (int s = 0; s < len; s++) {
        float v = (l < TTAGS) ? fv : -1e30f;
        #pragma unroll
        for (int o = 8; o; o >>= 1) v = fmaxf(v, __shfl_xor_sync(0xffffffffu, v, o));
        float e = (l < TTAGS) ? expf(fv - v) : 0.f;
        es[l] = e;
        __syncwarp();
        float sa = 0.f, sb = 0.f;
        #pragma unroll
        for (int p = 0; p < TTAGS; p += 2) {
            sa = fmaf(es[p],     et[p],     sa);
            sb = fmaf(es[p + 1], et[p + 1], sb);
        }
        if (l < TTAGS) fv = v + logf(sa + sb) + fb[s * TTAGS + l];
        __syncwarp();
    }

    float term = (l < TTAGS) ? (fv + trans[STOP_TAG * TTAGS + l]) : -1e30f;
    float mx = term;
    #pragma unroll
    for (int o = 16; o; o >>= 1) mx = fmaxf(mx, __shfl_xor_sync(0xffffffffu, mx, o));
    float e = (l < TTAGS) ? expf(term - mx) : 0.f;
    #pragma unroll
    for (int o = 16; o; o >>= 1) e += __shfl_xor_sync(0xffffffffu, e, o);
    if (l == 0) out[b] = (mx + logf(e)) / (float)len;
}

// ---------------------------------------------------------------------------
extern "C" void kernel_launch(void* const* d_in, const int* in_sizes, int n_in,
                              void* d_out, int out_size)
{
    const int*   tokens  = (const int*)  d_in[0];
    const int*   lengths = (const int*)  d_in[1];
    const float* emb     = (const float*)d_in[2];
    const float* w_ih_f  = (const float*)d_in[3];
    const float* w_hh_f  = (const float*)d_in[4];
    const float* b_f     = (const float*)d_in[5];
    const float* w_ih_b  = (const float*)d_in[6];
    const float* w_hh_b  = (const float*)d_in[7];
    const float* b_b     = (const float*)d_in[8];
    const float* w_out   = (const float*)d_in[9];
    const float* b_out   = (const float*)d_in[10];
    const float* trans   = (const float*)d_in[11];
    float* out = (float*)d_out;

    dummy_kernel<<<1, 32>>>();
    dummy_kernel<<<1, 32>>>();
    xg_kernel<<<dim3(64, 16, 2), 256>>>(tokens, emb, w_ih_f, b_f, w_ih_b, b_b);
    recur_kernel<<<128, 256>>>(w_hh_f, w_hh_b);
    feats_kernel<<<SEQ, 256>>>(w_out, b_out);
    crf_kernel<<<BATCH, 32>>>(lengths, trans, out);
}

// round 14
// speedup vs baseline: 2.9071x; 1.0644x over previous
#include <cuda_runtime.h>
#include <cuda_bf16.h>
#include <math.h>
#include <stdint.h>

// Problem dims (fixed)
#define SEQ 256
#define BATCH 32
#define EDIM 256
#define HDIM 512
#define GDIM 2048           // 4*H
#define TTAGS 10
#define START_TAG 8
#define STOP_TAG 9
#define NEGV -10000.0f

// fast activations (MUFU-based; |err| ~1e-6, budget 1e-3)
__device__ __forceinline__ float fsig(float x)  { return 1.f / (1.f + __expf(-x)); }
__device__ __forceinline__ float ftanh(float x) { return 1.f - 2.f / (__expf(2.f * x) + 1.f); }

// ---------------- scratch (static device globals; no runtime alloc) ----------
__device__ float g_xg2[2u * 4 * (SEQ * BATCH) * HDIM];   // [d][gate][m][j]
__device__ float g_hseq[2u * SEQ * BATCH * HDIM];        // f32 h for feats
// h as pre-packed mma B-fragment words: slot = (d*SEQ+t)*2+bh, 4096 words/slot.
// word idx = slot*4096 + ktile*128 + lane*4 + q, q = nt*2+reg  (LDG.128-friendly).
// Slot 1024 = zeros (step 0).
__device__ uint32_t g_hfrag_hi[1025u * 4096u];
__device__ uint32_t g_hfrag_lo[1025u * 4096u];
__device__ float g_feats[SEQ * BATCH * TTAGS];
__device__ int   g_cnt[4 * 32];                          // group counters at [g*32]

// m16n8k16 bf16 HMMA (sm_80+ baseline PTX; compiles for compute_103)
__device__ __forceinline__ void mma16816(float* c, const uint32_t* a, const uint32_t* b) {
    asm volatile(
        "mma.sync.aligned.m16n8k16.row.col.f32.bf16.bf16.f32 "
        "{%0,%1,%2,%3}, {%4,%5,%6,%7}, {%8,%9}, {%0,%1,%2,%3};"
        : "+f"(c[0]), "+f"(c[1]), "+f"(c[2]), "+f"(c[3])
        : "r"(a[0]), "r"(a[1]), "r"(a[2]), "r"(a[3]), "r"(b[0]), "r"(b[1]));
}

// split 16 f32 -> 16 bf16 hi + 16 bf16 lo, stored as 2x uint4 each
__device__ __forceinline__ void split16(const float* f, __nv_bfloat16* hi, __nv_bfloat16* lo) {
    uint32_t hw[8], lw[8];
    #pragma unroll
    for (int q = 0; q < 8; q++) {
        __nv_bfloat16 h0 = __float2bfloat16(f[2 * q]);
        __nv_bfloat16 h1 = __float2bfloat16(f[2 * q + 1]);
        __nv_bfloat16 l0 = __float2bfloat16(f[2 * q]     - __bfloat162float(h0));
        __nv_bfloat16 l1 = __float2bfloat16(f[2 * q + 1] - __bfloat162float(h1));
        hw[q] = (uint32_t)__bfloat16_as_ushort(h0) | ((uint32_t)__bfloat16_as_ushort(h1) << 16);
        lw[q] = (uint32_t)__bfloat16_as_ushort(l0) | ((uint32_t)__bfloat16_as_ushort(l1) << 16);
    }
    ((uint4*)hi)[0] = make_uint4(hw[0], hw[1], hw[2], hw[3]);
    ((uint4*)hi)[1] = make_uint4(hw[4], hw[5], hw[6], hw[7]);
    ((uint4*)lo)[0] = make_uint4(lw[0], lw[1], lw[2], lw[3]);
    ((uint4*)lo)[1] = make_uint4(lw[4], lw[5], lw[6], lw[7]);
}

// ---------------------------------------------------------------------------
__global__ void dummy_kernel() {}   // keeps ncu -s 5 window on recur_kernel

// ---------------------------------------------------------------------------
// Kernel 1: xg2[d][gate][m][j] via split-bf16 HMMA.
// Block 128(m) x 128(n), K=256 in 8 iters of 32. 8 warps (2m x 4n), warp 64x32.
// Smem rows stride 40 bf16 (conflict-free for (g,tq) fragment loads).
// Also resets the recurrence barrier counters.
// ---------------------------------------------------------------------------
__global__ void __launch_bounds__(256) xg_kernel(
    const int* __restrict__ tokens, const float* __restrict__ emb,
    const float* __restrict__ wf, const float* __restrict__ bf,
    const float* __restrict__ wb, const float* __restrict__ bb)
{
    const int bm = blockIdx.x;          // 64
    const int bn = blockIdx.y;          // 16
    const int dir = blockIdx.z;         // 2
    const int tid = threadIdx.x;

    if (bm == 0 && bn == 0 && dir == 0 && tid < 4) g_cnt[tid * 32] = 0;

    const float* wp   = dir ? wb : wf;
    const float* bias = dir ? bb : bf;

    __shared__ int rowtok[128];
    __shared__ __align__(16) __nv_bfloat16 sAhi[128 * 40];
    __shared__ __align__(16) __nv_bfloat16 sAlo[128 * 40];
    __shared__ __align__(16) __nv_bfloat16 sBhi[128 * 40];
    __shared__ __align__(16) __nv_bfloat16 sBlo[128 * 40];

    if (tid < 128) {
        int mg = bm * 128 + tid;                 // m = t*32 + b
        rowtok[tid] = tokens[(mg & 31) * SEQ + (mg >> 5)];
    }
    __syncthreads();

    const int w   = tid >> 5;
    const int lid = tid & 31;
    const int g   = lid >> 2;
    const int tq  = lid & 3;
    const int wm  = w & 1;              // warp m (2)
    const int wn  = w >> 1;             // warp n (4)

    float acc[4][4][4];
    #pragma unroll
    for (int mt = 0; mt < 4; mt++)
        #pragma unroll
        for (int nt = 0; nt < 4; nt++)
            #pragma unroll
            for (int q = 0; q < 4; q++) acc[mt][nt][q] = 0.f;

    const int r  = tid & 127;           // staging row
    const int kh = (tid >> 7) * 16;     // staging k-half

    for (int it = 0; it < 8; it++) {
        const int k0 = it * 32;
        // ---- stage A (gathered emb) and B (W rows), split hi/lo ----
        {
            float fa[16], fb2[16];
            const float4* asrc = (const float4*)(emb + (size_t)rowtok[r] * EDIM + k0 + kh);
            const float4* bsrc = (const float4*)(wp + (size_t)(bn * 128 + r) * EDIM + k0 + kh);
            #pragma unroll
            for (int i = 0; i < 4; i++) {
                float4 va = asrc[i];
                fa[4 * i] = va.x; fa[4 * i + 1] = va.y; fa[4 * i + 2] = va.z; fa[4 * i + 3] = va.w;
                float4 vb = bsrc[i];
                fb2[4 * i] = vb.x; fb2[4 * i + 1] = vb.y; fb2[4 * i + 2] = vb.z; fb2[4 * i + 3] = vb.w;
            }
            split16(fa, sAhi + r * 40 + kh, sAlo + r * 40 + kh);
            split16(fb2, sBhi + r * 40 + kh, sBlo + r * 40 + kh);
        }
        __syncthreads();

        #pragma unroll
        for (int kk = 0; kk < 2; kk++) {
            const int kb = kk * 16;
            uint32_t Ah[4][4], Al[4][4], Bh[4][2], Bl[4][2];
            #pragma unroll
            for (int mt = 0; mt < 4; mt++) {
                int o = (wm * 64 + mt * 16 + g) * 40 + kb + 2 * tq;
                Ah[mt][0] = *(const uint32_t*)(sAhi + o);
                Ah[mt][1] = *(const uint32_t*)(sAhi + o + 8 * 40);
                Ah[mt][2] = *(const uint32_t*)(sAhi + o + 8);
                Ah[mt][3] = *(const uint32_t*)(sAhi + o + 8 * 40 + 8);
                Al[mt][0] = *(const uint32_t*)(sAlo + o);
                Al[mt][1] = *(const uint32_t*)(sAlo + o + 8 * 40);
                Al[mt][2] = *(const uint32_t*)(sAlo + o + 8);
                Al[mt][3] = *(const uint32_t*)(sAlo + o + 8 * 40 + 8);
            }
            #pragma unroll
            for (int nt = 0; nt < 4; nt++) {
                int o = (wn * 32 + nt * 8 + g) * 40 + kb + 2 * tq;
                Bh[nt][0] = *(const uint32_t*)(sBhi + o);
                Bh[nt][1] = *(const uint32_t*)(sBhi + o + 8);
                Bl[nt][0] = *(const uint32_t*)(sBlo + o);
                Bl[nt][1] = *(const uint32_t*)(sBlo + o + 8);
            }
            #pragma unroll
            for (int mt = 0; mt < 4; mt++)
                #pragma unroll
                for (int nt = 0; nt < 4; nt++) {
                    mma16816(acc[mt][nt], Ah[mt], Bh[nt]);
                    mma16816(acc[mt][nt], Ah[mt], Bl[nt]);
                    mma16816(acc[mt][nt], Al[mt], Bh[nt]);
                }
        }
        __syncthreads();
    }

    // ---- epilogue: add bias, store f32 (full 32B sectors per (g,nt)) ----
    const int gate  = bn >> 2;
    const int jbase = (bn & 3) * 128 + wn * 32;
    #pragma unroll
    for (int nt = 0; nt < 4; nt++) {
        int j = jbase + nt * 8 + 2 * tq;
        int nglob = bn * 128 + wn * 32 + nt * 8 + 2 * tq;
        float b0 = bias[nglob], b1 = bias[nglob + 1];
        #pragma unroll
        for (int mt = 0; mt < 4; mt++) {
            int m = bm * 128 + wm * 64 + mt * 16 + g;
            float* p0 = g_xg2 + (((size_t)dir * 4 + gate) * 8192 + m) * HDIM + j;
            float* p1 = p0 + 8 * HDIM;   // row m+8
            *(float2*)p0 = make_float2(acc[mt][nt][0] + b0, acc[mt][nt][1] + b1);
            *(float2*)p1 = make_float2(acc[mt][nt][2] + b0, acc[mt][nt][3] + b1);
        }
    }
}

// ---------------------------------------------------------------------------
// Kernel 2: persistent BiLSTM recurrence on HMMA (unchanged from R12).
// ---------------------------------------------------------------------------
__global__ void __launch_bounds__(256, 1) recur_kernel(
    const float* __restrict__ whhf, const float* __restrict__ whhb)
{
    __shared__ float part[8 * 64 * 17];   // [w][row 0..63][b 0..15] padded

    const int tid = threadIdx.x;
    const int w   = tid >> 5;
    const int lid = tid & 31;
    const int g   = lid >> 2;             // mma groupID
    const int tq  = lid & 3;              // mma threadID_in_group

    const int bid   = blockIdx.x;
    const int dir   = bid >> 6;
    const int sub   = bid & 63;
    const int chunk = sub >> 1;            // 0..31, 16 units each
    const int bh    = sub & 1;
    const int j0    = chunk * 16;

    // cell role: one (u, bt) per thread
    const int u  = tid & 15;
    const int bt = tid >> 4;

    int* cnt = g_cnt + (dir * 2 + bh) * 32;

    // ---- one-time: W fragments (hi/lo split) into registers ----
    const float* whh = dir ? whhb : whhf;
    uint32_t ahi[4][4][4], alo[4][4][4];   // [mt=gate][kt][reg]
    #pragma unroll
    for (int mt = 0; mt < 4; mt++)
        #pragma unroll
        for (int kt = 0; kt < 4; kt++)
            #pragma unroll
            for (int reg = 0; reg < 4; reg++) {
                int urow = g + (reg & 1) * 8;              // within 16-unit tile
                int grow = mt * HDIM + j0 + urow;          // row in W[2048]
                int k    = w * 64 + kt * 16 + 2 * tq + (reg >> 1) * 8;
                float v0 = whh[(size_t)grow * HDIM + k];
                float v1 = whh[(size_t)grow * HDIM + k + 1];
                __nv_bfloat16 h0 = __float2bfloat16(v0);
                __nv_bfloat16 h1 = __float2bfloat16(v1);
                __nv_bfloat16 l0 = __float2bfloat16(v0 - __bfloat162float(h0));
                __nv_bfloat16 l1 = __float2bfloat16(v1 - __bfloat162float(h1));
                ahi[mt][kt][reg] = (uint32_t)__bfloat16_as_ushort(h0)
                                 | ((uint32_t)__bfloat16_as_ushort(h1) << 16);
                alo[mt][kt][reg] = (uint32_t)__bfloat16_as_ushort(l0)
                                 | ((uint32_t)__bfloat16_as_ushort(l1) << 16);
            }

    float c = 0.f;                         // cell state (dir, j0+u, bh*16+bt)

    for (int step = 0; step < SEQ; ++step) {
        const int t = dir ? (SEQ - 1 - step) : step;

        // ---- group barrier: REDG arrive; ALL lanes acquire-poll (same addr) ----
        __syncthreads();                   // h-frag stores of prev step done CTA-wide
        if (tid == 0)
            asm volatile("red.release.gpu.global.add.s32 [%0], %1;" :: "l"(cnt), "r"(1) : "memory");

        // xg prefetch (independent of h; issues before the poll loop)
        float xgv[4];
        #pragma unroll
        for (int gate = 0; gate < 4; gate++)
            xgv[gate] = __ldg(g_xg2 +
                ((size_t)(dir * 4 + gate) * 8192 + (size_t)t * 32 + bh * 16 + bt) * HDIM + j0 + u);

        {
            const int target = 32 * (step + 1);
            int v;
            do {
                asm volatile("ld.acquire.gpu.global.s32 %0, [%1];" : "=r"(v) : "l"(cnt) : "memory");
            } while (v < target);
        }

        // ---- load B fragments: 4 hi + 4 lo LDG.128 per thread ----
        const uint32_t slot = (step == 0) ? 1024u
            : (uint32_t)((dir * SEQ + (dir ? t + 1 : t - 1)) * 2 + bh);
        const uint4* bhp = (const uint4*)(g_hfrag_hi + (size_t)slot * 4096u) + (w * 4) * 32 + lid;
        const uint4* blp = (const uint4*)(g_hfrag_lo + (size_t)slot * 4096u) + (w * 4) * 32 + lid;
        uint32_t bhi[4][2][2], blo[4][2][2];
        #pragma unroll
        for (int kt = 0; kt < 4; kt++) {
            uint4 vh = bhp[kt * 32];
            uint4 vl = blp[kt * 32];
            bhi[kt][0][0] = vh.x; bhi[kt][0][1] = vh.y;
            bhi[kt][1][0] = vh.z; bhi[kt][1][1] = vh.w;
            blo[kt][0][0] = vl.x; blo[kt][0][1] = vl.y;
            blo[kt][1][0] = vl.z; blo[kt][1][1] = vl.w;
        }

        // ---- MMAs: (Whi+Wlo)(hhi+hlo) minus lo*lo ----
        float acc[4][2][4];
        #pragma unroll
        for (int mt = 0; mt < 4; mt++)
            #pragma unroll
            for (int nt = 0; nt < 2; nt++)
                #pragma unroll
                for (int q = 0; q < 4; q++) acc[mt][nt][q] = 0.f;
        #pragma unroll
        for (int kt = 0; kt < 4; kt++)
            #pragma unroll
            for (int mt = 0; mt < 4; mt++)
                #pragma unroll
                for (int nt = 0; nt < 2; nt++) {
                    mma16816(acc[mt][nt], ahi[mt][kt], bhi[kt][nt]);
                    mma16816(acc[mt][nt], ahi[mt][kt], blo[kt][nt]);
                    mma16816(acc[mt][nt], alo[mt][kt], bhi[kt][nt]);
                }

        // ---- write partials to smem ----
        #pragma unroll
        for (int mt = 0; mt < 4; mt++)
            #pragma unroll
            for (int nt = 0; nt < 2; nt++) {
                int row0 = mt * 16 + g;
                int col0 = nt * 8 + 2 * tq;
                part[(w * 64 + row0) * 17 + col0]         = acc[mt][nt][0];
                part[(w * 64 + row0) * 17 + col0 + 1]     = acc[mt][nt][1];
                part[(w * 64 + row0 + 8) * 17 + col0]     = acc[mt][nt][2];
                part[(w * 64 + row0 + 8) * 17 + col0 + 1] = acc[mt][nt][3];
            }
        __syncthreads();

        // ---- reduce across 8 k-slices + LSTM cell for (u, bt) ----
        float gi = xgv[0], gf = xgv[1], gg = xgv[2], go = xgv[3];
        #pragma unroll
        for (int kw = 0; kw < 8; kw++) {
            gi += part[(kw * 64 +  0 + u) * 17 + bt];
            gf += part[(kw * 64 + 16 + u) * 17 + bt];
            gg += part[(kw * 64 + 32 + u) * 17 + bt];
            go += part[(kw * 64 + 48 + u) * 17 + bt];
        }
        c = fsig(gf) * c + fsig(gi) * ftanh(gg);
        float h = fsig(go) * ftanh(c);

        g_hseq[((size_t)(dir * SEQ + t) * BATCH + bh * 16 + bt) * HDIM + j0 + u] = h;

        // ---- pack h into B-fragment words (pairs along u via shfl) ----
        float ho = __shfl_xor_sync(0xffffffffu, h, 1);   // partner u^1, same bt
        if ((u & 1) == 0) {
            __nv_bfloat16 hh0 = __float2bfloat16(h);
            __nv_bfloat16 hh1 = __float2bfloat16(ho);
            __nv_bfloat16 hl0 = __float2bfloat16(h  - __bfloat162float(hh0));
            __nv_bfloat16 hl1 = __float2bfloat16(ho - __bfloat162float(hh1));
            uint32_t whi = (uint32_t)__bfloat16_as_ushort(hh0)
                         | ((uint32_t)__bfloat16_as_ushort(hh1) << 16);
            uint32_t wlo = (uint32_t)__bfloat16_as_ushort(hl0)
                         | ((uint32_t)__bfloat16_as_ushort(hl1) << 16);
            int reg = u >> 3;
            int tq2 = (u & 7) >> 1;
            int nt2 = bt >> 3;
            int g2  = bt & 7;
            uint32_t slotW = (uint32_t)((dir * SEQ + t) * 2 + bh);
            size_t idx = (size_t)slotW * 4096u + (uint32_t)chunk * 128u
                       + (uint32_t)((g2 * 4 + tq2) * 4 + nt2 * 2 + reg);
            g_hfrag_hi[idx] = whi;
            g_hfrag_lo[idx] = wlo;
        }
    }
}

// ---------------------------------------------------------------------------
// Kernel 3: feats (unchanged)
// ---------------------------------------------------------------------------
__global__ void __launch_bounds__(256) feats_kernel(
    const float* __restrict__ w_out, const float* __restrict__ b_out)
{
    const int s = blockIdx.x;
    const int w = threadIdx.x >> 5;
    const int l = threadIdx.x & 31;

    for (int b = w; b < BATCH; b += 8) {
        const float* hf = g_hseq + ((size_t)(0 * SEQ + s) * BATCH + b) * HDIM;
        const float* hb = g_hseq + ((size_t)(1 * SEQ + s) * BATCH + b) * HDIM;
        float hv[32];
        #pragma unroll
        for (int i = 0; i < 16; i++) hv[i]      = hf[l + 32 * i];
        #pragma unroll
        for (int i = 0; i < 16; i++) hv[16 + i] = hb[l + 32 * i];
        for (int tag = 0; tag < TTAGS; tag++) {
            const float* wr = w_out + (size_t)tag * (2 * HDIM);
            float p = 0.f;
            #pragma unroll
            for (int i = 0; i < 16; i++) p = fmaf(hv[i],      wr[l + 32 * i],        p);
            #pragma unroll
            for (int i = 0; i < 16; i++) p = fmaf(hv[16 + i], wr[HDIM + l + 32 * i], p);
            #pragma unroll
            for (int o = 16; o; o >>= 1) p += __shfl_down_sync(0xffffffffu, p, o);
            if (l == 0) g_feats[(s * BATCH + b) * TTAGS + tag] = p + b_out[tag];
        }
    }
}

// ---------------------------------------------------------------------------
// Kernel 4: CRF forward (MUFU exp/log in the serial scan)
// ---------------------------------------------------------------------------
__global__ void __launch_bounds__(32) crf_kernel(
    const int* __restrict__ lengths, const float* __restrict__ trans,
    float* __restrict__ out)
{
    const int b = blockIdx.x;
    const int l = threadIdx.x;

    __shared__ float fb[SEQ * TTAGS];
    __shared__ float es[32];
    for (int i = l; i < SEQ * TTAGS; i += 32) {
        int s = i / TTAGS, tg = i - s * TTAGS;
        fb[i] = g_feats[(s * BATCH + b) * TTAGS + tg];
    }

    float et[TTAGS];
    if (l < TTAGS) {
        #pragma unroll
        for (int p = 0; p < TTAGS; p++) et[p] = __expf(trans[l * TTAGS + p]);
    }
    float fv = (l == START_TAG) ? 0.f : NEGV;
    es[l] = 0.f;
    __syncwarp();

    const int len = lengths[b];
    for (int s = 0; s < len; s++) {
        float v = (l < TTAGS) ? fv : -1e30f;
        #pragma unroll
        for (int o = 8; o; o >>= 1) v = fmaxf(v, __shfl_xor_sync(0xffffffffu, v, o));
        float e = (l < TTAGS) ? __expf(fv - v) : 0.f;
        es[l] = e;
        __syncwarp();
        float sa = 0.f, sb = 0.f;
        #pragma unroll
        for (int p = 0; p < TTAGS; p += 2) {
            sa = fmaf(es[p],     et[p],     sa);
            sb = fmaf(es[p + 1], et[p + 1], sb);
        }
        if (l < TTAGS) fv = v + __logf(sa + sb) + fb[s * TTAGS + l];
        __syncwarp();
    }

    float term = (l < TTAGS) ? (fv + trans[STOP_TAG * TTAGS + l]) : -1e30f;
    float mx = term;
    #pragma unroll
    for (int o = 16; o; o >>= 1) mx = fmaxf(mx, __shfl_xor_sync(0xffffffffu, mx, o));
    float e = (l < TTAGS) ? __expf(term - mx) : 0.f;
    #pragma unroll
    for (int o = 16; o; o >>= 1) e += __shfl_xor_sync(0xffffffffu, e, o);
    if (l == 0) out[b] = (mx + __logf(e)) / (float)len;
}

// ---------------------------------------------------------------------------
extern "C" void kernel_launch(void* const* d_in, const int* in_sizes, int n_in,
                              void* d_out, int out_size)
{
    const int*   tokens  = (const int*)  d_in[0];
    const int*   lengths = (const int*)  d_in[1];
    const float* emb     = (const float*)d_in[2];
    const float* w_ih_f  = (const float*)d_in[3];
    const float* w_hh_f  = (const float*)d_in[4];
    const float* b_f     = (const float*)d_in[5];
    const float* w_ih_b  = (const float*)d_in[6];
    const float* w_hh_b  = (const float*)d_in[7];
    const float* b_b     = (const float*)d_in[8];
    const float* w_out   = (const float*)d_in[9];
    const float* b_out   = (const float*)d_in[10];
    const float* trans   = (const float*)d_in[11];
    float* out = (float*)d_out;

    dummy_kernel<<<1, 32>>>();
    dummy_kernel<<<1, 32>>>();
    xg_kernel<<<dim3(64, 16, 2), 256>>>(tokens, emb, w_ih_f, b_f, w_ih_b, b_b);
    recur_kernel<<<128, 256>>>(w_hh_f, w_hh_b);
    feats_kernel<<<SEQ, 256>>>(w_out, b_out);
    crf_kernel<<<BATCH, 32>>>(lengths, trans, out);
}